// round 8
// baseline (speedup 1.0000x reference)
#include <cuda_runtime.h>
#include <cuda_bf16.h>
#include <cstdint>

typedef __nv_bfloat16 bf16;

#define BATCH 2
#define TQ    2048
#define HID   1280
#define NH    20
#define HD    64
#define CROSSD 2048
#define SENC  77
#define SPAD  128
#define FFD   5120
#define M1    (BATCH*TQ)     /* 4096 */
#define MENC  (BATCH*SENC)   /* 154  */
#define NBH   (BATCH*NH)     /* 40   */

// ---------------- scratch (device globals; no allocation) ----------------
__device__ float g_h   [M1*HID];
__device__ float g_p1  [M1*HID];
__device__ float g_p2  [M1*HID];
__device__ float g_p3  [M1*HID];
__device__ float g_qh  [(size_t)NBH*TQ*HD];
__device__ float g_kh  [(size_t)NBH*TQ*HD];
__device__ float g_vT  [(size_t)NBH*HD*TQ];
__device__ float g_scores[(size_t)NBH*TQ*TQ];   // fp32, softmax in-place
__device__ float g_att [M1*HID];
__device__ float g_x   [M1*HID];
__device__ float g_proj[(size_t)M1*2*FFD];
__device__ float g_ff  [(size_t)M1*FFD];

// ---------------- elementwise kernels ----------------
__global__ void ln_kernel(const float* __restrict__ x, const float* __restrict__ g,
                          const float* __restrict__ b, float* __restrict__ out) {
    __shared__ float red[256];
    int row = blockIdx.x, tid = threadIdx.x;
    const float* xr = x + (long long)row * HID;
    float v[5], s = 0.f;
#pragma unroll
    for (int i = 0; i < 5; i++) { v[i] = xr[tid + i * 256]; s += v[i]; }
    red[tid] = s; __syncthreads();
    for (int o = 128; o > 0; o >>= 1) { if (tid < o) red[tid] += red[tid + o]; __syncthreads(); }
    float mu = red[0] * (1.0f / HID);
    __syncthreads();
    float sq = 0.f;
#pragma unroll
    for (int i = 0; i < 5; i++) { float d = v[i] - mu; sq += d * d; }
    red[tid] = sq; __syncthreads();
    for (int o = 128; o > 0; o >>= 1) { if (tid < o) red[tid] += red[tid + o]; __syncthreads(); }
    float rs = rsqrtf(red[0] * (1.0f / HID) + 1e-5f);
#pragma unroll
    for (int i = 0; i < 5; i++) {
        int c = tid + i * 256;
        out[(long long)row * HID + c] = (v[i] - mu) * rs * g[c] + b[c];
    }
}

__global__ void reshape_q_kernel(const float* __restrict__ q, float* __restrict__ qh) {
    long long idx = (long long)blockIdx.x * blockDim.x + threadIdx.x;
    if (idx >= (long long)NBH * TQ * HD) return;
    int d = idx & (HD - 1);
    long long r = idx >> 6;
    int t = (int)(r % TQ);
    long long bh = r / TQ;
    int h = (int)(bh % NH), b = (int)(bh / NH);
    qh[idx] = q[((long long)(b * TQ + t)) * HID + h * HD + d];
}

__global__ void reshape_k_kernel(const float* __restrict__ k, float* __restrict__ kh, int S, int Spad) {
    long long idx = (long long)blockIdx.x * blockDim.x + threadIdx.x;
    long long tot = (long long)NBH * Spad * HD;
    if (idx >= tot) return;
    int d = idx & (HD - 1);
    long long r = idx >> 6;
    int s = (int)(r % Spad);
    long long bh = r / Spad;
    int h = (int)(bh % NH), b = (int)(bh / NH);
    float val = 0.f;
    if (s < S) val = k[((long long)(b * S + s)) * HID + h * HD + d];
    kh[idx] = val;
}

__global__ void reshape_vT_kernel(const float* __restrict__ v, float* __restrict__ vT, int S, int Spad) {
    long long idx = (long long)blockIdx.x * blockDim.x + threadIdx.x;
    long long tot = (long long)NBH * HD * Spad;
    if (idx >= tot) return;
    int s = (int)(idx % Spad);
    long long r = idx / Spad;
    int d = (int)(r % HD);
    long long bh = r / HD;
    int h = (int)(bh % NH), b = (int)(bh / NH);
    float val = 0.f;
    if (s < S) val = v[((long long)(b * S + s)) * HID + h * HD + d];
    vT[idx] = val;
}

__global__ void softmax_kernel(float* __restrict__ S, int Spad, int Sval) {
    __shared__ float red[256];
    long long row = blockIdx.x;
    float* sr = S + row * (long long)Spad;
    int tid = threadIdx.x;
    float vals[8];
    int cnt = 0;
    float mx = -1e30f;
    for (int j = tid; j < Sval; j += 256) { float v = sr[j]; vals[cnt++] = v; mx = fmaxf(mx, v); }
    red[tid] = mx; __syncthreads();
    for (int o = 128; o > 0; o >>= 1) { if (tid < o) red[tid] = fmaxf(red[tid], red[tid + o]); __syncthreads(); }
    mx = red[0]; __syncthreads();
    float sum = 0.f;
    for (int i = 0; i < cnt; i++) { vals[i] = expf(vals[i] - mx); sum += vals[i]; }
    red[tid] = sum; __syncthreads();
    for (int o = 128; o > 0; o >>= 1) { if (tid < o) red[tid] += red[tid + o]; __syncthreads(); }
    float inv = 1.f / red[0];
    cnt = 0;
    for (int j = tid; j < Spad; j += 256) {
        float o = (j < Sval) ? vals[cnt++] * inv : 0.f;
        sr[j] = o;
    }
}

__global__ void geglu_kernel(const float* __restrict__ proj, float* __restrict__ out) {
    long long i = (long long)blockIdx.x * blockDim.x + threadIdx.x;
    if (i >= (long long)M1 * FFD) return;
    long long r = i / FFD;
    int c = (int)(i % FFD);
    float x1 = proj[r * (2 * FFD) + c];
    float x2 = proj[r * (2 * FFD) + FFD + c];
    float gel = 0.5f * x2 * (1.0f + erff(x2 * 0.7071067811865476f));
    out[i] = x1 * gel;
}

// ---------------- pipelined batched split-bf16 tensor-core GEMM ----------------
// C[z][M][N] = scale * (A[z] @ W[z]^T) + bias + residual   (fp32 in/out)
// A = Ah + Al, W = Wh + Wl (bf16 hi/lo); product = Ah*Wh + Ah*Wl + Al*Wh in fp32.
// 2-stage double-buffered smem, 1 __syncthreads per k-tile, LDG reg prefetch.
// __launch_bounds__(256,2): cap regs at 128 -> 2 CTAs/SM -> 4 warps/SMSP latency hiding.
__device__ __forceinline__ void mma16816(float c[4], const uint32_t a[4], const uint32_t b[2]) {
    asm volatile(
        "mma.sync.aligned.m16n8k16.row.col.f32.bf16.bf16.f32 "
        "{%0,%1,%2,%3}, {%4,%5,%6,%7}, {%8,%9}, {%0,%1,%2,%3};\n"
        : "+f"(c[0]), "+f"(c[1]), "+f"(c[2]), "+f"(c[3])
        : "r"(a[0]), "r"(a[1]), "r"(a[2]), "r"(a[3]), "r"(b[0]), "r"(b[1]));
}

#define TILE_ELE (128 * 40)
#define SMEM_BYTES (8 * TILE_ELE * 2)   /* 81920 */

__global__ __launch_bounds__(256, 2) void gemm_kernel(
    const float* __restrict__ A, const float* __restrict__ W,
    const float* __restrict__ bias, const float* __restrict__ residual,
    float* __restrict__ C,
    int M, int N, int K,
    long long aStride, long long wStride,
    long long cHi, long long cLo, int cDiv, int ldc, float scale)
{
    extern __shared__ __align__(16) bf16 sm[];
    bf16* sAh = sm;                 // [2][128][40]
    bf16* sAl = sm + 2 * TILE_ELE;
    bf16* sBh = sm + 4 * TILE_ELE;
    bf16* sBl = sm + 6 * TILE_ELE;

    int z = blockIdx.z;
    A += (long long)z * aStride;
    W += (long long)z * wStride;
    long long cOff = (long long)(z / cDiv) * cHi + (long long)(z % cDiv) * cLo;

    int tid = threadIdx.x;
    int lane = tid & 31, warp = tid >> 5;
    int wm = warp >> 1, wn = warp & 1;
    int rowBase = blockIdx.y * 128;
    int colBase = blockIdx.x * 128;

    // load mapping: thread covers 4 float4 per operand per tile
    int lr[4], lc[4];
#pragma unroll
    for (int it = 0; it < 4; ++it) {
        int i = tid + it * 256;
        lr[it] = i >> 3;
        lc[it] = (i & 7) << 2;
    }

    float acc[2][8][4];
#pragma unroll
    for (int i = 0; i < 2; i++)
#pragma unroll
        for (int j = 0; j < 8; j++)
#pragma unroll
            for (int l = 0; l < 4; l++) acc[i][j][l] = 0.f;

    float4 pa[4], pb[4];

    int kTiles = K >> 5;

    // prefetch tile 0
#pragma unroll
    for (int it = 0; it < 4; ++it) {
        int gr = rowBase + lr[it];
        pa[it] = (gr < M) ? *(const float4*)(A + (long long)gr * K + lc[it])
                          : make_float4(0.f, 0.f, 0.f, 0.f);
        int gn = colBase + lr[it];
        pb[it] = (gn < N) ? *(const float4*)(W + (long long)gn * K + lc[it])
                          : make_float4(0.f, 0.f, 0.f, 0.f);
    }

    for (int kt = 0; kt < kTiles; ++kt) {
        int s = kt & 1;
        // store prefetched regs -> smem stage s (hi/lo split, packed 32-bit stores)
        {
            bf16* Ah = sAh + s * TILE_ELE;
            bf16* Al = sAl + s * TILE_ELE;
            bf16* Bh = sBh + s * TILE_ELE;
            bf16* Bl = sBl + s * TILE_ELE;
#pragma unroll
            for (int it = 0; it < 4; ++it) {
                int off = lr[it] * 40 + lc[it];
                float4 va = pa[it];
                __nv_bfloat162 h0 = __floats2bfloat162_rn(va.x, va.y);
                __nv_bfloat162 h1 = __floats2bfloat162_rn(va.z, va.w);
                __nv_bfloat162 l0 = __floats2bfloat162_rn(va.x - __bfloat162float(h0.x),
                                                          va.y - __bfloat162float(h0.y));
                __nv_bfloat162 l1 = __floats2bfloat162_rn(va.z - __bfloat162float(h1.x),
                                                          va.w - __bfloat162float(h1.y));
                *(__nv_bfloat162*)(Ah + off)     = h0;
                *(__nv_bfloat162*)(Ah + off + 2) = h1;
                *(__nv_bfloat162*)(Al + off)     = l0;
                *(__nv_bfloat162*)(Al + off + 2) = l1;
                float4 vb = pb[it];
                h0 = __floats2bfloat162_rn(vb.x, vb.y);
                h1 = __floats2bfloat162_rn(vb.z, vb.w);
                l0 = __floats2bfloat162_rn(vb.x - __bfloat162float(h0.x),
                                           vb.y - __bfloat162float(h0.y));
                l1 = __floats2bfloat162_rn(vb.z - __bfloat162float(h1.x),
                                           vb.w - __bfloat162float(h1.y));
                *(__nv_bfloat162*)(Bh + off)     = h0;
                *(__nv_bfloat162*)(Bh + off + 2) = h1;
                *(__nv_bfloat162*)(Bl + off)     = l0;
                *(__nv_bfloat162*)(Bl + off + 2) = l1;
            }
        }
        __syncthreads();

        // prefetch next tile into regs (LDG latency overlapped with compute)
        if (kt + 1 < kTiles) {
            int k0 = (kt + 1) << 5;
#pragma unroll
            for (int it = 0; it < 4; ++it) {
                int gr = rowBase + lr[it];
                pa[it] = (gr < M) ? *(const float4*)(A + (long long)gr * K + k0 + lc[it])
                                  : make_float4(0.f, 0.f, 0.f, 0.f);
                int gn = colBase + lr[it];
                pb[it] = (gn < N) ? *(const float4*)(W + (long long)gn * K + k0 + lc[it])
                                  : make_float4(0.f, 0.f, 0.f, 0.f);
            }
        }

        // compute on stage s
        const bf16* Ah = sAh + s * TILE_ELE;
        const bf16* Al = sAl + s * TILE_ELE;
        const bf16* Bh = sBh + s * TILE_ELE;
        const bf16* Bl = sBl + s * TILE_ELE;
#pragma unroll
        for (int kk = 0; kk < 32; kk += 16) {
            uint32_t ah[2][4], al[2][4];
#pragma unroll
            for (int mt = 0; mt < 2; ++mt) {
                int r = wm * 32 + mt * 16 + (lane >> 2);
                int c = kk + (lane & 3) * 2;
                ah[mt][0] = *(const uint32_t*)(Ah + r * 40 + c);
                ah[mt][1] = *(const uint32_t*)(Ah + (r + 8) * 40 + c);
                ah[mt][2] = *(const uint32_t*)(Ah + r * 40 + c + 8);
                ah[mt][3] = *(const uint32_t*)(Ah + (r + 8) * 40 + c + 8);
                al[mt][0] = *(const uint32_t*)(Al + r * 40 + c);
                al[mt][1] = *(const uint32_t*)(Al + (r + 8) * 40 + c);
                al[mt][2] = *(const uint32_t*)(Al + r * 40 + c + 8);
                al[mt][3] = *(const uint32_t*)(Al + (r + 8) * 40 + c + 8);
            }
#pragma unroll
            for (int nt = 0; nt < 8; ++nt) {
                int n = wn * 64 + nt * 8 + (lane >> 2);
                int c = kk + (lane & 3) * 2;
                uint32_t bh[2], bl[2];
                bh[0] = *(const uint32_t*)(Bh + n * 40 + c);
                bh[1] = *(const uint32_t*)(Bh + n * 40 + c + 8);
                bl[0] = *(const uint32_t*)(Bl + n * 40 + c);
                bl[1] = *(const uint32_t*)(Bl + n * 40 + c + 8);
#pragma unroll
                for (int mt = 0; mt < 2; ++mt) {
                    mma16816(acc[mt][nt], ah[mt], bh);
                    mma16816(acc[mt][nt], ah[mt], bl);
                    mma16816(acc[mt][nt], al[mt], bh);
                }
            }
        }
    }

#pragma unroll
    for (int mt = 0; mt < 2; ++mt)
#pragma unroll
        for (int nt = 0; nt < 8; ++nt) {
            int col = colBase + wn * 64 + nt * 8 + (lane & 3) * 2;
            if (col >= N) continue;
#pragma unroll
            for (int i = 0; i < 2; ++i) {
                int row = rowBase + wm * 32 + mt * 16 + (lane >> 2) + i * 8;
                if (row >= M) continue;
                float v0 = acc[mt][nt][i * 2 + 0] * scale;
                float v1 = acc[mt][nt][i * 2 + 1] * scale;
                if (bias) { v0 += bias[col]; v1 += bias[col + 1]; }
                long long o = cOff + (long long)row * ldc + col;
                if (residual) { v0 += residual[o]; v1 += residual[o + 1]; }
                C[o] = v0; C[o + 1] = v1;
            }
        }
}

// ---------------- host glue ----------------
static void gemm(const float* A, const float* W, const float* bias, const float* res,
                 float* C, int M, int N, int K, int Z,
                 long long aS, long long wS, long long cHi, long long cLo, int cDiv,
                 int ldc, float scale) {
    dim3 g((N + 127) / 128, (M + 127) / 128, Z);
    gemm_kernel<<<g, 256, SMEM_BYTES>>>(A, W, bias, res, C, M, N, K, aS, wS, cHi, cLo, cDiv, ldc, scale);
}

extern "C" void kernel_launch(void* const* d_in, const int* in_sizes, int n_in,
                              void* d_out, int out_size) {
    const float* x     = (const float*)d_in[0];
    const float* enc   = (const float*)d_in[1];
    const float* ln1g  = (const float*)d_in[2];
    const float* ln1b  = (const float*)d_in[3];
    const float* ln2g  = (const float*)d_in[4];
    const float* ln2b  = (const float*)d_in[5];
    const float* ln3g  = (const float*)d_in[6];
    const float* ln3b  = (const float*)d_in[7];
    const float* wq1   = (const float*)d_in[8];
    const float* wk1   = (const float*)d_in[9];
    const float* wv1   = (const float*)d_in[10];
    const float* wo1   = (const float*)d_in[11];
    const float* bo1   = (const float*)d_in[12];
    const float* wq2   = (const float*)d_in[13];
    const float* wk2   = (const float*)d_in[14];
    const float* wv2   = (const float*)d_in[15];
    const float* wo2   = (const float*)d_in[16];
    const float* bo2   = (const float*)d_in[17];
    const float* wgg   = (const float*)d_in[18];
    const float* bgg   = (const float*)d_in[19];
    const float* wff   = (const float*)d_in[20];
    const float* bff   = (const float*)d_in[21];
    float* out = (float*)d_out;

    static bool attr_done = false;
    if (!attr_done) {
        cudaFuncSetAttribute(gemm_kernel, cudaFuncAttributeMaxDynamicSharedMemorySize, SMEM_BYTES);
        attr_done = true;
    }

    float *h, *p1, *p2, *p3, *qh, *kh, *vT, *scores, *att, *xcur, *proj, *ff;
    cudaGetSymbolAddress((void**)&h,      g_h);
    cudaGetSymbolAddress((void**)&p1,     g_p1);
    cudaGetSymbolAddress((void**)&p2,     g_p2);
    cudaGetSymbolAddress((void**)&p3,     g_p3);
    cudaGetSymbolAddress((void**)&qh,     g_qh);
    cudaGetSymbolAddress((void**)&kh,     g_kh);
    cudaGetSymbolAddress((void**)&vT,     g_vT);
    cudaGetSymbolAddress((void**)&scores, g_scores);
    cudaGetSymbolAddress((void**)&att,    g_att);
    cudaGetSymbolAddress((void**)&xcur,   g_x);
    cudaGetSymbolAddress((void**)&proj,   g_proj);
    cudaGetSymbolAddress((void**)&ff,     g_ff);

    // ---- self attention ----
    ln_kernel<<<M1, 256>>>(x, ln1g, ln1b, h);
    gemm(h, wq1, nullptr, nullptr, p1, M1, HID, HID, 1, 0, 0, 0, 0, 1, HID, 1.f);
    gemm(h, wk1, nullptr, nullptr, p2, M1, HID, HID, 1, 0, 0, 0, 0, 1, HID, 1.f);
    gemm(h, wv1, nullptr, nullptr, p3, M1, HID, HID, 1, 0, 0, 0, 0, 1, HID, 1.f);
    {
        long long nq = (long long)NBH * TQ * HD;
        reshape_q_kernel<<<(unsigned)((nq + 255) / 256), 256>>>(p1, qh);
        reshape_k_kernel<<<(unsigned)((nq + 255) / 256), 256>>>(p2, kh, TQ, TQ);
        reshape_vT_kernel<<<(unsigned)((nq + 255) / 256), 256>>>(p3, vT, TQ, TQ);
    }
    gemm(qh, kh, nullptr, nullptr, scores, TQ, TQ, HD, NBH,
         (long long)TQ * HD, (long long)TQ * HD, (long long)TQ * TQ, 0, 1, TQ, 0.125f);
    softmax_kernel<<<NBH * TQ, 256>>>(scores, TQ, TQ);
    gemm(scores, vT, nullptr, nullptr, att, TQ, HD, TQ, NBH,
         (long long)TQ * TQ, (long long)HD * TQ,
         (long long)TQ * HID, (long long)HD, NH, HID, 1.f);
    gemm(att, wo1, bo1, x, xcur, M1, HID, HID, 1, 0, 0, 0, 0, 1, HID, 1.f);

    // ---- cross attention ----
    ln_kernel<<<M1, 256>>>(xcur, ln2g, ln2b, h);
    gemm(h, wq2, nullptr, nullptr, p1, M1, HID, HID, 1, 0, 0, 0, 0, 1, HID, 1.f);
    gemm(enc, wk2, nullptr, nullptr, p2, MENC, HID, CROSSD, 1, 0, 0, 0, 0, 1, HID, 1.f);
    gemm(enc, wv2, nullptr, nullptr, p3, MENC, HID, CROSSD, 1, 0, 0, 0, 0, 1, HID, 1.f);
    {
        long long nq = (long long)NBH * TQ * HD;
        long long nk = (long long)NBH * SPAD * HD;
        reshape_q_kernel<<<(unsigned)((nq + 255) / 256), 256>>>(p1, qh);
        reshape_k_kernel<<<(unsigned)((nk + 255) / 256), 256>>>(p2, kh, SENC, SPAD);
        reshape_vT_kernel<<<(unsigned)((nk + 255) / 256), 256>>>(p3, vT, SENC, SPAD);
    }
    gemm(qh, kh, nullptr, nullptr, scores, TQ, SPAD, HD, NBH,
         (long long)TQ * HD, (long long)SPAD * HD, (long long)TQ * SPAD, 0, 1, SPAD, 0.125f);
    softmax_kernel<<<NBH * TQ, 256>>>(scores, SPAD, SENC);
    gemm(scores, vT, nullptr, nullptr, att, TQ, HD, SPAD, NBH,
         (long long)TQ * SPAD, (long long)HD * SPAD,
         (long long)TQ * HID, (long long)HD, NH, HID, 1.f);
    gemm(att, wo2, bo2, xcur, xcur, M1, HID, HID, 1, 0, 0, 0, 0, 1, HID, 1.f);

    // ---- GEGLU FF ----
    ln_kernel<<<M1, 256>>>(xcur, ln3g, ln3b, h);
    gemm(h, wgg, bgg, nullptr, proj, M1, 2 * FFD, HID, 1, 0, 0, 0, 0, 1, 2 * FFD, 1.f);
    {
        long long n = (long long)M1 * FFD;
        geglu_kernel<<<(unsigned)((n + 255) / 256), 256>>>(proj, ff);
    }
    gemm(ff, wff, bff, xcur, out, M1, HID, FFD, 1, 0, 0, 0, 0, 1, HID, 1.f);

    (void)in_sizes; (void)n_in; (void)out_size;
}

// round 9
// speedup vs baseline: 1.5067x; 1.5067x over previous
#include <cuda_runtime.h>
#include <cuda_bf16.h>
#include <cstdint>

typedef __nv_bfloat16 bf16;

#define BATCH 2
#define TQ    2048
#define HID   1280
#define NH    20
#define HD    64
#define CROSSD 2048
#define SENC  77
#define SPAD  128
#define FFD   5120
#define M1    (BATCH*TQ)     /* 4096 */
#define MENC  (BATCH*SENC)   /* 154  */
#define NBH   (BATCH*NH)     /* 40   */

// ---------------- scratch (device globals; no allocation) ----------------
__device__ float g_h   [M1*HID];
__device__ float g_p1  [M1*HID];
__device__ float g_p2  [M1*HID];
__device__ float g_p3  [M1*HID];
__device__ float g_qh  [(size_t)NBH*TQ*HD];
__device__ float g_kh  [(size_t)NBH*TQ*HD];
__device__ float g_vT  [(size_t)NBH*HD*TQ];
__device__ float g_scores[(size_t)NBH*TQ*TQ];   // fp32, softmax in-place
__device__ float g_att [M1*HID];
__device__ float g_x   [M1*HID];
__device__ float g_proj[(size_t)M1*2*FFD];
__device__ float g_ff  [(size_t)M1*FFD];

// ---------------- elementwise kernels ----------------
__global__ void ln_kernel(const float* __restrict__ x, const float* __restrict__ g,
                          const float* __restrict__ b, float* __restrict__ out) {
    __shared__ float red[256];
    int row = blockIdx.x, tid = threadIdx.x;
    const float* xr = x + (long long)row * HID;
    float v[5], s = 0.f;
#pragma unroll
    for (int i = 0; i < 5; i++) { v[i] = xr[tid + i * 256]; s += v[i]; }
    red[tid] = s; __syncthreads();
    for (int o = 128; o > 0; o >>= 1) { if (tid < o) red[tid] += red[tid + o]; __syncthreads(); }
    float mu = red[0] * (1.0f / HID);
    __syncthreads();
    float sq = 0.f;
#pragma unroll
    for (int i = 0; i < 5; i++) { float d = v[i] - mu; sq += d * d; }
    red[tid] = sq; __syncthreads();
    for (int o = 128; o > 0; o >>= 1) { if (tid < o) red[tid] += red[tid + o]; __syncthreads(); }
    float rs = rsqrtf(red[0] * (1.0f / HID) + 1e-5f);
#pragma unroll
    for (int i = 0; i < 5; i++) {
        int c = tid + i * 256;
        out[(long long)row * HID + c] = (v[i] - mu) * rs * g[c] + b[c];
    }
}

__global__ void reshape_q_kernel(const float* __restrict__ q, float* __restrict__ qh) {
    long long idx = (long long)blockIdx.x * blockDim.x + threadIdx.x;
    if (idx >= (long long)NBH * TQ * HD) return;
    int d = idx & (HD - 1);
    long long r = idx >> 6;
    int t = (int)(r % TQ);
    long long bh = r / TQ;
    int h = (int)(bh % NH), b = (int)(bh / NH);
    qh[idx] = q[((long long)(b * TQ + t)) * HID + h * HD + d];
}

__global__ void reshape_k_kernel(const float* __restrict__ k, float* __restrict__ kh, int S, int Spad) {
    long long idx = (long long)blockIdx.x * blockDim.x + threadIdx.x;
    long long tot = (long long)NBH * Spad * HD;
    if (idx >= tot) return;
    int d = idx & (HD - 1);
    long long r = idx >> 6;
    int s = (int)(r % Spad);
    long long bh = r / Spad;
    int h = (int)(bh % NH), b = (int)(bh / NH);
    float val = 0.f;
    if (s < S) val = k[((long long)(b * S + s)) * HID + h * HD + d];
    kh[idx] = val;
}

__global__ void reshape_vT_kernel(const float* __restrict__ v, float* __restrict__ vT, int S, int Spad) {
    long long idx = (long long)blockIdx.x * blockDim.x + threadIdx.x;
    long long tot = (long long)NBH * HD * Spad;
    if (idx >= tot) return;
    int s = (int)(idx % Spad);
    long long r = idx / Spad;
    int d = (int)(r % HD);
    long long bh = r / HD;
    int h = (int)(bh % NH), b = (int)(bh / NH);
    float val = 0.f;
    if (s < S) val = v[((long long)(b * S + s)) * HID + h * HD + d];
    vT[idx] = val;
}

__global__ void softmax_kernel(float* __restrict__ S, int Spad, int Sval) {
    __shared__ float red[256];
    long long row = blockIdx.x;
    float* sr = S + row * (long long)Spad;
    int tid = threadIdx.x;
    float vals[8];
    int cnt = 0;
    float mx = -1e30f;
    for (int j = tid; j < Sval; j += 256) { float v = sr[j]; vals[cnt++] = v; mx = fmaxf(mx, v); }
    red[tid] = mx; __syncthreads();
    for (int o = 128; o > 0; o >>= 1) { if (tid < o) red[tid] = fmaxf(red[tid], red[tid + o]); __syncthreads(); }
    mx = red[0]; __syncthreads();
    float sum = 0.f;
    for (int i = 0; i < cnt; i++) { vals[i] = expf(vals[i] - mx); sum += vals[i]; }
    red[tid] = sum; __syncthreads();
    for (int o = 128; o > 0; o >>= 1) { if (tid < o) red[tid] += red[tid + o]; __syncthreads(); }
    float inv = 1.f / red[0];
    cnt = 0;
    for (int j = tid; j < Spad; j += 256) {
        float o = (j < Sval) ? vals[cnt++] * inv : 0.f;
        sr[j] = o;
    }
}

__global__ void geglu_kernel(const float* __restrict__ proj, float* __restrict__ out) {
    long long i = (long long)blockIdx.x * blockDim.x + threadIdx.x;
    if (i >= (long long)M1 * FFD) return;
    long long r = i / FFD;
    int c = (int)(i % FFD);
    float x1 = proj[r * (2 * FFD) + c];
    float x2 = proj[r * (2 * FFD) + FFD + c];
    float gel = 0.5f * x2 * (1.0f + erff(x2 * 0.7071067811865476f));
    out[i] = x1 * gel;
}

// ---------------- pipelined batched split-bf16 tensor-core GEMM ----------------
// C[z][M][N] = scale * (A[z] @ W[z]^T) + bias + residual   (fp32 in/out)
// A = Ah + Al, W = Wh + Wl (bf16 hi/lo); product = Ah*Wh + Ah*Wl + Al*Wh in fp32.
// CTA tile 128x128x32, 512 threads (16 warps, 4x4, warp tile 32x32).
// 2-stage double-buffered smem, 1 __syncthreads per k-tile, LDG reg prefetch.
// ~100 regs/thread -> 16 warps resident -> 4 warps/SMSP latency hiding, no spills.
__device__ __forceinline__ void mma16816(float c[4], const uint32_t a[4], const uint32_t b[2]) {
    asm volatile(
        "mma.sync.aligned.m16n8k16.row.col.f32.bf16.bf16.f32 "
        "{%0,%1,%2,%3}, {%4,%5,%6,%7}, {%8,%9}, {%0,%1,%2,%3};\n"
        : "+f"(c[0]), "+f"(c[1]), "+f"(c[2]), "+f"(c[3])
        : "r"(a[0]), "r"(a[1]), "r"(a[2]), "r"(a[3]), "r"(b[0]), "r"(b[1]));
}

#define TILE_ELE (128 * 40)
#define SMEM_BYTES (8 * TILE_ELE * 2)   /* 81920 */

__global__ __launch_bounds__(512, 1) void gemm_kernel(
    const float* __restrict__ A, const float* __restrict__ W,
    const float* __restrict__ bias, const float* __restrict__ residual,
    float* __restrict__ C,
    int M, int N, int K,
    long long aStride, long long wStride,
    long long cHi, long long cLo, int cDiv, int ldc, float scale)
{
    extern __shared__ __align__(16) bf16 sm[];
    bf16* sAh = sm;                 // [2][128][40]
    bf16* sAl = sm + 2 * TILE_ELE;
    bf16* sBh = sm + 4 * TILE_ELE;
    bf16* sBl = sm + 6 * TILE_ELE;

    int z = blockIdx.z;
    A += (long long)z * aStride;
    W += (long long)z * wStride;
    long long cOff = (long long)(z / cDiv) * cHi + (long long)(z % cDiv) * cLo;

    int tid = threadIdx.x;
    int lane = tid & 31, warp = tid >> 5;
    int wm = warp >> 2, wn = warp & 3;      // 4x4 warp grid, 32x32 warp tile
    int rowBase = blockIdx.y * 128;
    int colBase = blockIdx.x * 128;
    bool wactive = (colBase + wn * 32) < N; // skip compute for fully-OOB col groups (PV N=64)

    // load mapping: thread covers 2 float4 per operand per tile
    int lr[2], lc[2];
#pragma unroll
    for (int it = 0; it < 2; ++it) {
        int i = tid + it * 512;
        lr[it] = i >> 3;
        lc[it] = (i & 7) << 2;
    }

    float acc[2][4][4];
#pragma unroll
    for (int i = 0; i < 2; i++)
#pragma unroll
        for (int j = 0; j < 4; j++)
#pragma unroll
            for (int l = 0; l < 4; l++) acc[i][j][l] = 0.f;

    float4 pa[2], pb[2];

    int kTiles = K >> 5;

    // prefetch tile 0
#pragma unroll
    for (int it = 0; it < 2; ++it) {
        int gr = rowBase + lr[it];
        pa[it] = (gr < M) ? *(const float4*)(A + (long long)gr * K + lc[it])
                          : make_float4(0.f, 0.f, 0.f, 0.f);
        int gn = colBase + lr[it];
        pb[it] = (gn < N) ? *(const float4*)(W + (long long)gn * K + lc[it])
                          : make_float4(0.f, 0.f, 0.f, 0.f);
    }

    for (int kt = 0; kt < kTiles; ++kt) {
        int s = kt & 1;
        // store prefetched regs -> smem stage s (hi/lo split, packed 32-bit stores)
        {
            bf16* Ah = sAh + s * TILE_ELE;
            bf16* Al = sAl + s * TILE_ELE;
            bf16* Bh = sBh + s * TILE_ELE;
            bf16* Bl = sBl + s * TILE_ELE;
#pragma unroll
            for (int it = 0; it < 2; ++it) {
                int off = lr[it] * 40 + lc[it];
                float4 va = pa[it];
                __nv_bfloat162 h0 = __floats2bfloat162_rn(va.x, va.y);
                __nv_bfloat162 h1 = __floats2bfloat162_rn(va.z, va.w);
                __nv_bfloat162 l0 = __floats2bfloat162_rn(va.x - __bfloat162float(h0.x),
                                                          va.y - __bfloat162float(h0.y));
                __nv_bfloat162 l1 = __floats2bfloat162_rn(va.z - __bfloat162float(h1.x),
                                                          va.w - __bfloat162float(h1.y));
                *(__nv_bfloat162*)(Ah + off)     = h0;
                *(__nv_bfloat162*)(Ah + off + 2) = h1;
                *(__nv_bfloat162*)(Al + off)     = l0;
                *(__nv_bfloat162*)(Al + off + 2) = l1;
                float4 vb = pb[it];
                h0 = __floats2bfloat162_rn(vb.x, vb.y);
                h1 = __floats2bfloat162_rn(vb.z, vb.w);
                l0 = __floats2bfloat162_rn(vb.x - __bfloat162float(h0.x),
                                           vb.y - __bfloat162float(h0.y));
                l1 = __floats2bfloat162_rn(vb.z - __bfloat162float(h1.x),
                                           vb.w - __bfloat162float(h1.y));
                *(__nv_bfloat162*)(Bh + off)     = h0;
                *(__nv_bfloat162*)(Bh + off + 2) = h1;
                *(__nv_bfloat162*)(Bl + off)     = l0;
                *(__nv_bfloat162*)(Bl + off + 2) = l1;
            }
        }
        __syncthreads();

        // prefetch next tile into regs (LDG latency overlapped with compute)
        if (kt + 1 < kTiles) {
            int k0 = (kt + 1) << 5;
#pragma unroll
            for (int it = 0; it < 2; ++it) {
                int gr = rowBase + lr[it];
                pa[it] = (gr < M) ? *(const float4*)(A + (long long)gr * K + k0 + lc[it])
                                  : make_float4(0.f, 0.f, 0.f, 0.f);
                int gn = colBase + lr[it];
                pb[it] = (gn < N) ? *(const float4*)(W + (long long)gn * K + k0 + lc[it])
                                  : make_float4(0.f, 0.f, 0.f, 0.f);
            }
        }

        // compute on stage s
        if (wactive) {
            const bf16* Ah = sAh + s * TILE_ELE;
            const bf16* Al = sAl + s * TILE_ELE;
            const bf16* Bh = sBh + s * TILE_ELE;
            const bf16* Bl = sBl + s * TILE_ELE;
#pragma unroll
            for (int kk = 0; kk < 32; kk += 16) {
                uint32_t ah[2][4], al[2][4];
#pragma unroll
                for (int mt = 0; mt < 2; ++mt) {
                    int r = wm * 32 + mt * 16 + (lane >> 2);
                    int c = kk + (lane & 3) * 2;
                    ah[mt][0] = *(const uint32_t*)(Ah + r * 40 + c);
                    ah[mt][1] = *(const uint32_t*)(Ah + (r + 8) * 40 + c);
                    ah[mt][2] = *(const uint32_t*)(Ah + r * 40 + c + 8);
                    ah[mt][3] = *(const uint32_t*)(Ah + (r + 8) * 40 + c + 8);
                    al[mt][0] = *(const uint32_t*)(Al + r * 40 + c);
                    al[mt][1] = *(const uint32_t*)(Al + (r + 8) * 40 + c);
                    al[mt][2] = *(const uint32_t*)(Al + r * 40 + c + 8);
                    al[mt][3] = *(const uint32_t*)(Al + (r + 8) * 40 + c + 8);
                }
#pragma unroll
                for (int nt = 0; nt < 4; ++nt) {
                    int n = wn * 32 + nt * 8 + (lane >> 2);
                    int c = kk + (lane & 3) * 2;
                    uint32_t bh[2], bl[2];
                    bh[0] = *(const uint32_t*)(Bh + n * 40 + c);
                    bh[1] = *(const uint32_t*)(Bh + n * 40 + c + 8);
                    bl[0] = *(const uint32_t*)(Bl + n * 40 + c);
                    bl[1] = *(const uint32_t*)(Bl + n * 40 + c + 8);
#pragma unroll
                    for (int mt = 0; mt < 2; ++mt) {
                        mma16816(acc[mt][nt], ah[mt], bh);
                        mma16816(acc[mt][nt], ah[mt], bl);
                        mma16816(acc[mt][nt], al[mt], bh);
                    }
                }
            }
        }
        __syncthreads();
    }

    if (wactive) {
#pragma unroll
        for (int mt = 0; mt < 2; ++mt)
#pragma unroll
            for (int nt = 0; nt < 4; ++nt) {
                int col = colBase + wn * 32 + nt * 8 + (lane & 3) * 2;
                if (col >= N) continue;
#pragma unroll
                for (int i = 0; i < 2; ++i) {
                    int row = rowBase + wm * 32 + mt * 16 + (lane >> 2) + i * 8;
                    if (row >= M) continue;
                    float v0 = acc[mt][nt][i * 2 + 0] * scale;
                    float v1 = acc[mt][nt][i * 2 + 1] * scale;
                    if (bias) { v0 += bias[col]; v1 += bias[col + 1]; }
                    long long o = cOff + (long long)row * ldc + col;
                    if (residual) { v0 += residual[o]; v1 += residual[o + 1]; }
                    C[o] = v0; C[o + 1] = v1;
                }
            }
    }
}

// ---------------- host glue ----------------
static void gemm(const float* A, const float* W, const float* bias, const float* res,
                 float* C, int M, int N, int K, int Z,
                 long long aS, long long wS, long long cHi, long long cLo, int cDiv,
                 int ldc, float scale) {
    dim3 g((N + 127) / 128, (M + 127) / 128, Z);
    gemm_kernel<<<g, 512, SMEM_BYTES>>>(A, W, bias, res, C, M, N, K, aS, wS, cHi, cLo, cDiv, ldc, scale);
}

extern "C" void kernel_launch(void* const* d_in, const int* in_sizes, int n_in,
                              void* d_out, int out_size) {
    const float* x     = (const float*)d_in[0];
    const float* enc   = (const float*)d_in[1];
    const float* ln1g  = (const float*)d_in[2];
    const float* ln1b  = (const float*)d_in[3];
    const float* ln2g  = (const float*)d_in[4];
    const float* ln2b  = (const float*)d_in[5];
    const float* ln3g  = (const float*)d_in[6];
    const float* ln3b  = (const float*)d_in[7];
    const float* wq1   = (const float*)d_in[8];
    const float* wk1   = (const float*)d_in[9];
    const float* wv1   = (const float*)d_in[10];
    const float* wo1   = (const float*)d_in[11];
    const float* bo1   = (const float*)d_in[12];
    const float* wq2   = (const float*)d_in[13];
    const float* wk2   = (const float*)d_in[14];
    const float* wv2   = (const float*)d_in[15];
    const float* wo2   = (const float*)d_in[16];
    const float* bo2   = (const float*)d_in[17];
    const float* wgg   = (const float*)d_in[18];
    const float* bgg   = (const float*)d_in[19];
    const float* wff   = (const float*)d_in[20];
    const float* bff   = (const float*)d_in[21];
    float* out = (float*)d_out;

    static bool attr_done = false;
    if (!attr_done) {
        cudaFuncSetAttribute(gemm_kernel, cudaFuncAttributeMaxDynamicSharedMemorySize, SMEM_BYTES);
        attr_done = true;
    }

    float *h, *p1, *p2, *p3, *qh, *kh, *vT, *scores, *att, *xcur, *proj, *ff;
    cudaGetSymbolAddress((void**)&h,      g_h);
    cudaGetSymbolAddress((void**)&p1,     g_p1);
    cudaGetSymbolAddress((void**)&p2,     g_p2);
    cudaGetSymbolAddress((void**)&p3,     g_p3);
    cudaGetSymbolAddress((void**)&qh,     g_qh);
    cudaGetSymbolAddress((void**)&kh,     g_kh);
    cudaGetSymbolAddress((void**)&vT,     g_vT);
    cudaGetSymbolAddress((void**)&scores, g_scores);
    cudaGetSymbolAddress((void**)&att,    g_att);
    cudaGetSymbolAddress((void**)&xcur,   g_x);
    cudaGetSymbolAddress((void**)&proj,   g_proj);
    cudaGetSymbolAddress((void**)&ff,     g_ff);

    // ---- self attention ----
    ln_kernel<<<M1, 256>>>(x, ln1g, ln1b, h);
    gemm(h, wq1, nullptr, nullptr, p1, M1, HID, HID, 1, 0, 0, 0, 0, 1, HID, 1.f);
    gemm(h, wk1, nullptr, nullptr, p2, M1, HID, HID, 1, 0, 0, 0, 0, 1, HID, 1.f);
    gemm(h, wv1, nullptr, nullptr, p3, M1, HID, HID, 1, 0, 0, 0, 0, 1, HID, 1.f);
    {
        long long nq = (long long)NBH * TQ * HD;
        reshape_q_kernel<<<(unsigned)((nq + 255) / 256), 256>>>(p1, qh);
        reshape_k_kernel<<<(unsigned)((nq + 255) / 256), 256>>>(p2, kh, TQ, TQ);
        reshape_vT_kernel<<<(unsigned)((nq + 255) / 256), 256>>>(p3, vT, TQ, TQ);
    }
    gemm(qh, kh, nullptr, nullptr, scores, TQ, TQ, HD, NBH,
         (long long)TQ * HD, (long long)TQ * HD, (long long)TQ * TQ, 0, 1, TQ, 0.125f);
    softmax_kernel<<<NBH * TQ, 256>>>(scores, TQ, TQ);
    gemm(scores, vT, nullptr, nullptr, att, TQ, HD, TQ, NBH,
         (long long)TQ * TQ, (long long)HD * TQ,
         (long long)TQ * HID, (long long)HD, NH, HID, 1.f);
    gemm(att, wo1, bo1, x, xcur, M1, HID, HID, 1, 0, 0, 0, 0, 1, HID, 1.f);

    // ---- cross attention ----
    ln_kernel<<<M1, 256>>>(xcur, ln2g, ln2b, h);
    gemm(h, wq2, nullptr, nullptr, p1, M1, HID, HID, 1, 0, 0, 0, 0, 1, HID, 1.f);
    gemm(enc, wk2, nullptr, nullptr, p2, MENC, HID, CROSSD, 1, 0, 0, 0, 0, 1, HID, 1.f);
    gemm(enc, wv2, nullptr, nullptr, p3, MENC, HID, CROSSD, 1, 0, 0, 0, 0, 1, HID, 1.f);
    {
        long long nq = (long long)NBH * TQ * HD;
        long long nk = (long long)NBH * SPAD * HD;
        reshape_q_kernel<<<(unsigned)((nq + 255) / 256), 256>>>(p1, qh);
        reshape_k_kernel<<<(unsigned)((nk + 255) / 256), 256>>>(p2, kh, SENC, SPAD);
        reshape_vT_kernel<<<(unsigned)((nk + 255) / 256), 256>>>(p3, vT, SENC, SPAD);
    }
    gemm(qh, kh, nullptr, nullptr, scores, TQ, SPAD, HD, NBH,
         (long long)TQ * HD, (long long)SPAD * HD, (long long)TQ * SPAD, 0, 1, SPAD, 0.125f);
    softmax_kernel<<<NBH * TQ, 256>>>(scores, SPAD, SENC);
    gemm(scores, vT, nullptr, nullptr, att, TQ, HD, SPAD, NBH,
         (long long)TQ * SPAD, (long long)HD * SPAD,
         (long long)TQ * HID, (long long)HD, NH, HID, 1.f);
    gemm(att, wo2, bo2, xcur, xcur, M1, HID, HID, 1, 0, 0, 0, 0, 1, HID, 1.f);

    // ---- GEGLU FF ----
    ln_kernel<<<M1, 256>>>(xcur, ln3g, ln3b, h);
    gemm(h, wgg, bgg, nullptr, proj, M1, 2 * FFD, HID, 1, 0, 0, 0, 0, 1, 2 * FFD, 1.f);
    {
        long long n = (long long)M1 * FFD;
        geglu_kernel<<<(unsigned)((n + 255) / 256), 256>>>(proj, ff);
    }
    gemm(ff, wff, bff, xcur, out, M1, HID, FFD, 1, 0, 0, 0, 0, 1, HID, 1.f);

    (void)in_sizes; (void)n_in; (void)out_size;
}

// round 10
// speedup vs baseline: 2.2637x; 1.5024x over previous
#include <cuda_runtime.h>
#include <cuda_fp16.h>
#include <cstdint>

#define BATCH 2
#define TQ    2048
#define HID   1280
#define NH    20
#define HD    64
#define CROSSD 2048
#define SENC  77
#define SPAD  128
#define FFD   5120
#define M1    (BATCH*TQ)     /* 4096 */
#define MENC  (BATCH*SENC)   /* 154  */
#define NBH   (BATCH*NH)     /* 40   */

// ---------------- scratch (device globals; no allocation) ----------------
__device__ float g_h   [M1*HID];
__device__ float g_p1  [M1*HID];
__device__ float g_p2  [M1*HID];
__device__ float g_p3  [M1*HID];
__device__ float g_qh  [(size_t)NBH*TQ*HD];
__device__ float g_kh  [(size_t)NBH*TQ*HD];
__device__ float g_vT  [(size_t)NBH*HD*TQ];
__device__ float g_scores[(size_t)NBH*TQ*TQ];   // fp32, softmax in-place
__device__ float g_att [M1*HID];
__device__ float g_x   [M1*HID];
__device__ float g_proj[(size_t)M1*2*FFD];
__device__ float g_ff  [(size_t)M1*FFD];

// ---------------- elementwise kernels ----------------
__global__ void ln_kernel(const float* __restrict__ x, const float* __restrict__ g,
                          const float* __restrict__ b, float* __restrict__ out) {
    __shared__ float red[256];
    int row = blockIdx.x, tid = threadIdx.x;
    const float* xr = x + (long long)row * HID;
    float v[5], s = 0.f;
#pragma unroll
    for (int i = 0; i < 5; i++) { v[i] = xr[tid + i * 256]; s += v[i]; }
    red[tid] = s; __syncthreads();
    for (int o = 128; o > 0; o >>= 1) { if (tid < o) red[tid] += red[tid + o]; __syncthreads(); }
    float mu = red[0] * (1.0f / HID);
    __syncthreads();
    float sq = 0.f;
#pragma unroll
    for (int i = 0; i < 5; i++) { float d = v[i] - mu; sq += d * d; }
    red[tid] = sq; __syncthreads();
    for (int o = 128; o > 0; o >>= 1) { if (tid < o) red[tid] += red[tid + o]; __syncthreads(); }
    float rs = rsqrtf(red[0] * (1.0f / HID) + 1e-5f);
#pragma unroll
    for (int i = 0; i < 5; i++) {
        int c = tid + i * 256;
        out[(long long)row * HID + c] = (v[i] - mu) * rs * g[c] + b[c];
    }
}

__global__ void reshape_q_kernel(const float* __restrict__ q, float* __restrict__ qh) {
    long long idx = (long long)blockIdx.x * blockDim.x + threadIdx.x;
    if (idx >= (long long)NBH * TQ * HD) return;
    int d = idx & (HD - 1);
    long long r = idx >> 6;
    int t = (int)(r % TQ);
    long long bh = r / TQ;
    int h = (int)(bh % NH), b = (int)(bh / NH);
    qh[idx] = q[((long long)(b * TQ + t)) * HID + h * HD + d];
}

__global__ void reshape_k_kernel(const float* __restrict__ k, float* __restrict__ kh, int S, int Spad) {
    long long idx = (long long)blockIdx.x * blockDim.x + threadIdx.x;
    long long tot = (long long)NBH * Spad * HD;
    if (idx >= tot) return;
    int d = idx & (HD - 1);
    long long r = idx >> 6;
    int s = (int)(r % Spad);
    long long bh = r / Spad;
    int h = (int)(bh % NH), b = (int)(bh / NH);
    float val = 0.f;
    if (s < S) val = k[((long long)(b * S + s)) * HID + h * HD + d];
    kh[idx] = val;
}

__global__ void reshape_vT_kernel(const float* __restrict__ v, float* __restrict__ vT, int S, int Spad) {
    long long idx = (long long)blockIdx.x * blockDim.x + threadIdx.x;
    long long tot = (long long)NBH * HD * Spad;
    if (idx >= tot) return;
    int s = (int)(idx % Spad);
    long long r = idx / Spad;
    int d = (int)(r % HD);
    long long bh = r / HD;
    int h = (int)(bh % NH), b = (int)(bh / NH);
    float val = 0.f;
    if (s < S) val = v[((long long)(b * S + s)) * HID + h * HD + d];
    vT[idx] = val;
}

__global__ void softmax_kernel(float* __restrict__ S, int Spad, int Sval) {
    __shared__ float red[256];
    long long row = blockIdx.x;
    float* sr = S + row * (long long)Spad;
    int tid = threadIdx.x;
    float vals[8];
    int cnt = 0;
    float mx = -1e30f;
    for (int j = tid; j < Sval; j += 256) { float v = sr[j]; vals[cnt++] = v; mx = fmaxf(mx, v); }
    red[tid] = mx; __syncthreads();
    for (int o = 128; o > 0; o >>= 1) { if (tid < o) red[tid] = fmaxf(red[tid], red[tid + o]); __syncthreads(); }
    mx = red[0]; __syncthreads();
    float sum = 0.f;
    for (int i = 0; i < cnt; i++) { vals[i] = expf(vals[i] - mx); sum += vals[i]; }
    red[tid] = sum; __syncthreads();
    for (int o = 128; o > 0; o >>= 1) { if (tid < o) red[tid] += red[tid + o]; __syncthreads(); }
    float inv = 1.f / red[0];
    cnt = 0;
    for (int j = tid; j < Spad; j += 256) {
        float o = (j < Sval) ? vals[cnt++] * inv : 0.f;
        sr[j] = o;
    }
}

__global__ void geglu_kernel(const float* __restrict__ proj, float* __restrict__ out) {
    long long i = (long long)blockIdx.x * blockDim.x + threadIdx.x;
    if (i >= (long long)M1 * FFD) return;
    long long r = i / FFD;
    int c = (int)(i % FFD);
    float x1 = proj[r * (2 * FFD) + c];
    float x2 = proj[r * (2 * FFD) + FFD + c];
    float gel = 0.5f * x2 * (1.0f + erff(x2 * 0.7071067811865476f));
    out[i] = x1 * gel;
}

// ---------------- pipelined batched fp16 tensor-core GEMM ----------------
// C[z][M][N] = scale * (A[z] @ W[z]^T) + bias + residual   (fp32 in/out)
// Operands rounded to fp16 (2^-11 rounding, ~8x finer than bf16); fp32 accumulate.
// CTA tile 128x128x32, 512 threads (16 warps 4x4, warp tile 32x32).
// 2-stage double-buffered smem, LDG reg prefetch, 1 MMA term (no split).
__device__ __forceinline__ void mma16816(float c[4], const uint32_t a[4], const uint32_t b[2]) {
    asm volatile(
        "mma.sync.aligned.m16n8k16.row.col.f32.f16.f16.f32 "
        "{%0,%1,%2,%3}, {%4,%5,%6,%7}, {%8,%9}, {%0,%1,%2,%3};\n"
        : "+f"(c[0]), "+f"(c[1]), "+f"(c[2]), "+f"(c[3])
        : "r"(a[0]), "r"(a[1]), "r"(a[2]), "r"(a[3]), "r"(b[0]), "r"(b[1]));
}

#define TILE_ELE (128 * 40)
#define SMEM_BYTES (4 * TILE_ELE * 2)   /* 40960: 2 stages x (A,B) */

__device__ __forceinline__ uint32_t h2_u32(__half2 v) {
    return *reinterpret_cast<uint32_t*>(&v);
}

__global__ __launch_bounds__(512, 1) void gemm_kernel(
    const float* __restrict__ A, const float* __restrict__ W,
    const float* __restrict__ bias, const float* __restrict__ residual,
    float* __restrict__ C,
    int M, int N, int K,
    long long aStride, long long wStride,
    long long cHi, long long cLo, int cDiv, int ldc, float scale)
{
    extern __shared__ __align__(16) __half sm[];
    __half* sA = sm;                 // [2][128][40]
    __half* sB = sm + 2 * TILE_ELE;

    int z = blockIdx.z;
    A += (long long)z * aStride;
    W += (long long)z * wStride;
    long long cOff = (long long)(z / cDiv) * cHi + (long long)(z % cDiv) * cLo;

    int tid = threadIdx.x;
    int lane = tid & 31, warp = tid >> 5;
    int wm = warp >> 2, wn = warp & 3;      // 4x4 warp grid, 32x32 warp tile
    int rowBase = blockIdx.y * 128;
    int colBase = blockIdx.x * 128;
    bool wactive = (colBase + wn * 32) < N; // skip fully-OOB col groups (PV N=64)

    // load mapping: thread covers 2 float4 per operand per tile
    int lr[2], lc[2];
#pragma unroll
    for (int it = 0; it < 2; ++it) {
        int i = tid + it * 512;
        lr[it] = i >> 3;
        lc[it] = (i & 7) << 2;
    }

    float acc[2][4][4];
#pragma unroll
    for (int i = 0; i < 2; i++)
#pragma unroll
        for (int j = 0; j < 4; j++)
#pragma unroll
            for (int l = 0; l < 4; l++) acc[i][j][l] = 0.f;

    float4 pa[2], pb[2];

    int kTiles = K >> 5;

    // prefetch tile 0
#pragma unroll
    for (int it = 0; it < 2; ++it) {
        int gr = rowBase + lr[it];
        pa[it] = (gr < M) ? *(const float4*)(A + (long long)gr * K + lc[it])
                          : make_float4(0.f, 0.f, 0.f, 0.f);
        int gn = colBase + lr[it];
        pb[it] = (gn < N) ? *(const float4*)(W + (long long)gn * K + lc[it])
                          : make_float4(0.f, 0.f, 0.f, 0.f);
    }

    for (int kt = 0; kt < kTiles; ++kt) {
        int s = kt & 1;
        // store prefetched regs -> smem stage s (fp16 convert, 8B stores)
        {
            __half* Ah = sA + s * TILE_ELE;
            __half* Bh = sB + s * TILE_ELE;
#pragma unroll
            for (int it = 0; it < 2; ++it) {
                int off = lr[it] * 40 + lc[it];
                float4 va = pa[it];
                __half2 a0 = __float22half2_rn(make_float2(va.x, va.y));
                __half2 a1 = __float22half2_rn(make_float2(va.z, va.w));
                *(uint2*)(Ah + off) = make_uint2(h2_u32(a0), h2_u32(a1));
                float4 vb = pb[it];
                __half2 b0 = __float22half2_rn(make_float2(vb.x, vb.y));
                __half2 b1 = __float22half2_rn(make_float2(vb.z, vb.w));
                *(uint2*)(Bh + off) = make_uint2(h2_u32(b0), h2_u32(b1));
            }
        }
        __syncthreads();

        // prefetch next tile into regs (LDG latency overlapped with compute)
        if (kt + 1 < kTiles) {
            int k0 = (kt + 1) << 5;
#pragma unroll
            for (int it = 0; it < 2; ++it) {
                int gr = rowBase + lr[it];
                pa[it] = (gr < M) ? *(const float4*)(A + (long long)gr * K + k0 + lc[it])
                                  : make_float4(0.f, 0.f, 0.f, 0.f);
                int gn = colBase + lr[it];
                pb[it] = (gn < N) ? *(const float4*)(W + (long long)gn * K + k0 + lc[it])
                                  : make_float4(0.f, 0.f, 0.f, 0.f);
            }
        }

        // compute on stage s
        if (wactive) {
            const __half* Ah = sA + s * TILE_ELE;
            const __half* Bh = sB + s * TILE_ELE;
#pragma unroll
            for (int kk = 0; kk < 32; kk += 16) {
                uint32_t a[2][4];
#pragma unroll
                for (int mt = 0; mt < 2; ++mt) {
                    int r = wm * 32 + mt * 16 + (lane >> 2);
                    int c = kk + (lane & 3) * 2;
                    a[mt][0] = *(const uint32_t*)(Ah + r * 40 + c);
                    a[mt][1] = *(const uint32_t*)(Ah + (r + 8) * 40 + c);
                    a[mt][2] = *(const uint32_t*)(Ah + r * 40 + c + 8);
                    a[mt][3] = *(const uint32_t*)(Ah + (r + 8) * 40 + c + 8);
                }
#pragma unroll
                for (int nt = 0; nt < 4; ++nt) {
                    int n = wn * 32 + nt * 8 + (lane >> 2);
                    int c = kk + (lane & 3) * 2;
                    uint32_t b[2];
                    b[0] = *(const uint32_t*)(Bh + n * 40 + c);
                    b[1] = *(const uint32_t*)(Bh + n * 40 + c + 8);
#pragma unroll
                    for (int mt = 0; mt < 2; ++mt)
                        mma16816(acc[mt][nt], a[mt], b);
                }
            }
        }
        __syncthreads();
    }

    if (wactive) {
#pragma unroll
        for (int mt = 0; mt < 2; ++mt)
#pragma unroll
            for (int nt = 0; nt < 4; ++nt) {
                int col = colBase + wn * 32 + nt * 8 + (lane & 3) * 2;
                if (col >= N) continue;
#pragma unroll
                for (int i = 0; i < 2; ++i) {
                    int row = rowBase + wm * 32 + mt * 16 + (lane >> 2) + i * 8;
                    if (row >= M) continue;
                    float v0 = acc[mt][nt][i * 2 + 0] * scale;
                    float v1 = acc[mt][nt][i * 2 + 1] * scale;
                    if (bias) { v0 += bias[col]; v1 += bias[col + 1]; }
                    long long o = cOff + (long long)row * ldc + col;
                    if (residual) { v0 += residual[o]; v1 += residual[o + 1]; }
                    C[o] = v0; C[o + 1] = v1;
                }
            }
    }
}

// ---------------- host glue ----------------
static void gemm(const float* A, const float* W, const float* bias, const float* res,
                 float* C, int M, int N, int K, int Z,
                 long long aS, long long wS, long long cHi, long long cLo, int cDiv,
                 int ldc, float scale) {
    dim3 g((N + 127) / 128, (M + 127) / 128, Z);
    gemm_kernel<<<g, 512, SMEM_BYTES>>>(A, W, bias, res, C, M, N, K, aS, wS, cHi, cLo, cDiv, ldc, scale);
}

extern "C" void kernel_launch(void* const* d_in, const int* in_sizes, int n_in,
                              void* d_out, int out_size) {
    const float* x     = (const float*)d_in[0];
    const float* enc   = (const float*)d_in[1];
    const float* ln1g  = (const float*)d_in[2];
    const float* ln1b  = (const float*)d_in[3];
    const float* ln2g  = (const float*)d_in[4];
    const float* ln2b  = (const float*)d_in[5];
    const float* ln3g  = (const float*)d_in[6];
    const float* ln3b  = (const float*)d_in[7];
    const float* wq1   = (const float*)d_in[8];
    const float* wk1   = (const float*)d_in[9];
    const float* wv1   = (const float*)d_in[10];
    const float* wo1   = (const float*)d_in[11];
    const float* bo1   = (const float*)d_in[12];
    const float* wq2   = (const float*)d_in[13];
    const float* wk2   = (const float*)d_in[14];
    const float* wv2   = (const float*)d_in[15];
    const float* wo2   = (const float*)d_in[16];
    const float* bo2   = (const float*)d_in[17];
    const float* wgg   = (const float*)d_in[18];
    const float* bgg   = (const float*)d_in[19];
    const float* wff   = (const float*)d_in[20];
    const float* bff   = (const float*)d_in[21];
    float* out = (float*)d_out;

    float *h, *p1, *p2, *p3, *qh, *kh, *vT, *scores, *att, *xcur, *proj, *ff;
    cudaGetSymbolAddress((void**)&h,      g_h);
    cudaGetSymbolAddress((void**)&p1,     g_p1);
    cudaGetSymbolAddress((void**)&p2,     g_p2);
    cudaGetSymbolAddress((void**)&p3,     g_p3);
    cudaGetSymbolAddress((void**)&qh,     g_qh);
    cudaGetSymbolAddress((void**)&kh,     g_kh);
    cudaGetSymbolAddress((void**)&vT,     g_vT);
    cudaGetSymbolAddress((void**)&scores, g_scores);
    cudaGetSymbolAddress((void**)&att,    g_att);
    cudaGetSymbolAddress((void**)&xcur,   g_x);
    cudaGetSymbolAddress((void**)&proj,   g_proj);
    cudaGetSymbolAddress((void**)&ff,     g_ff);

    // ---- self attention ----
    ln_kernel<<<M1, 256>>>(x, ln1g, ln1b, h);
    gemm(h, wq1, nullptr, nullptr, p1, M1, HID, HID, 1, 0, 0, 0, 0, 1, HID, 1.f);
    gemm(h, wk1, nullptr, nullptr, p2, M1, HID, HID, 1, 0, 0, 0, 0, 1, HID, 1.f);
    gemm(h, wv1, nullptr, nullptr, p3, M1, HID, HID, 1, 0, 0, 0, 0, 1, HID, 1.f);
    {
        long long nq = (long long)NBH * TQ * HD;
        reshape_q_kernel<<<(unsigned)((nq + 255) / 256), 256>>>(p1, qh);
        reshape_k_kernel<<<(unsigned)((nq + 255) / 256), 256>>>(p2, kh, TQ, TQ);
        reshape_vT_kernel<<<(unsigned)((nq + 255) / 256), 256>>>(p3, vT, TQ, TQ);
    }
    gemm(qh, kh, nullptr, nullptr, scores, TQ, TQ, HD, NBH,
         (long long)TQ * HD, (long long)TQ * HD, (long long)TQ * TQ, 0, 1, TQ, 0.125f);
    softmax_kernel<<<NBH * TQ, 256>>>(scores, TQ, TQ);
    gemm(scores, vT, nullptr, nullptr, att, TQ, HD, TQ, NBH,
         (long long)TQ * TQ, (long long)HD * TQ,
         (long long)TQ * HID, (long long)HD, NH, HID, 1.f);
    gemm(att, wo1, bo1, x, xcur, M1, HID, HID, 1, 0, 0, 0, 0, 1, HID, 1.f);

    // ---- cross attention ----
    ln_kernel<<<M1, 256>>>(xcur, ln2g, ln2b, h);
    gemm(h, wq2, nullptr, nullptr, p1, M1, HID, HID, 1, 0, 0, 0, 0, 1, HID, 1.f);
    gemm(enc, wk2, nullptr, nullptr, p2, MENC, HID, CROSSD, 1, 0, 0, 0, 0, 1, HID, 1.f);
    gemm(enc, wv2, nullptr, nullptr, p3, MENC, HID, CROSSD, 1, 0, 0, 0, 0, 1, HID, 1.f);
    {
        long long nq = (long long)NBH * TQ * HD;
        long long nk = (long long)NBH * SPAD * HD;
        reshape_q_kernel<<<(unsigned)((nq + 255) / 256), 256>>>(p1, qh);
        reshape_k_kernel<<<(unsigned)((nk + 255) / 256), 256>>>(p2, kh, SENC, SPAD);
        reshape_vT_kernel<<<(unsigned)((nk + 255) / 256), 256>>>(p3, vT, SENC, SPAD);
    }
    gemm(qh, kh, nullptr, nullptr, scores, TQ, SPAD, HD, NBH,
         (long long)TQ * HD, (long long)SPAD * HD, (long long)TQ * SPAD, 0, 1, SPAD, 0.125f);
    softmax_kernel<<<NBH * TQ, 256>>>(scores, SPAD, SENC);
    gemm(scores, vT, nullptr, nullptr, att, TQ, HD, SPAD, NBH,
         (long long)TQ * SPAD, (long long)HD * SPAD,
         (long long)TQ * HID, (long long)HD, NH, HID, 1.f);
    gemm(att, wo2, bo2, xcur, xcur, M1, HID, HID, 1, 0, 0, 0, 0, 1, HID, 1.f);

    // ---- GEGLU FF ----
    ln_kernel<<<M1, 256>>>(xcur, ln3g, ln3b, h);
    gemm(h, wgg, bgg, nullptr, proj, M1, 2 * FFD, HID, 1, 0, 0, 0, 0, 1, 2 * FFD, 1.f);
    {
        long long n = (long long)M1 * FFD;
        geglu_kernel<<<(unsigned)((n + 255) / 256), 256>>>(proj, ff);
    }
    gemm(ff, wff, bff, xcur, out, M1, HID, FFD, 1, 0, 0, 0, 0, 1, HID, 1.f);

    (void)in_sizes; (void)n_in; (void)out_size;
}

// round 11
// speedup vs baseline: 2.8031x; 1.2383x over previous
#include <cuda_runtime.h>
#include <cuda_fp16.h>
#include <cstdint>

#define BATCH 2
#define TQ    2048
#define HID   1280
#define NH    20
#define HD    64
#define CROSSD 2048
#define SENC  77
#define SPAD  128
#define FFD   5120
#define M1    (BATCH*TQ)     /* 4096 */
#define MENC  (BATCH*SENC)   /* 154  */
#define NBH   (BATCH*NH)     /* 40   */

typedef __half h16;

// ---------------- scratch (device globals; no allocation) ----------------
__device__ h16   g_h   [M1*HID];
__device__ h16   g_p1  [M1*HID];
__device__ h16   g_p2  [M1*HID];
__device__ h16   g_p3  [M1*HID];
__device__ h16   g_qh  [(size_t)NBH*TQ*HD];
__device__ h16   g_kh  [(size_t)NBH*TQ*HD];
__device__ h16   g_vT  [(size_t)NBH*HD*TQ];
__device__ float g_scores[(size_t)NBH*TQ*TQ];   // fp32 scores
__device__ h16   g_probs [(size_t)NBH*TQ*TQ];   // fp16 probs
__device__ h16   g_att [M1*HID];
__device__ float g_x   [M1*HID];
__device__ float g_proj[(size_t)M1*2*FFD];
__device__ h16   g_ff  [(size_t)M1*FFD];
__device__ h16   g_enc [MENC*CROSSD];
// fp16 weights
__device__ h16 g_wq1h[HID*HID];
__device__ h16 g_wk1h[HID*HID];
__device__ h16 g_wv1h[HID*HID];
__device__ h16 g_wo1h[HID*HID];
__device__ h16 g_wq2h[HID*HID];
__device__ h16 g_wk2h[HID*CROSSD];
__device__ h16 g_wv2h[HID*CROSSD];
__device__ h16 g_wo2h[HID*HID];
__device__ h16 g_wggh[2*FFD*HID];
__device__ h16 g_wffh[HID*FFD];

// ---------------- elementwise kernels ----------------
__global__ void f2h_kernel(const float* __restrict__ in, h16* __restrict__ out, long long n) {
    long long i = (long long)blockIdx.x * blockDim.x + threadIdx.x;
    if (i < n) out[i] = __float2half(in[i]);
}

__global__ void ln_kernel(const float* __restrict__ x, const float* __restrict__ g,
                          const float* __restrict__ b, h16* __restrict__ out) {
    __shared__ float red[256];
    int row = blockIdx.x, tid = threadIdx.x;
    const float* xr = x + (long long)row * HID;
    float v[5], s = 0.f;
#pragma unroll
    for (int i = 0; i < 5; i++) { v[i] = xr[tid + i * 256]; s += v[i]; }
    red[tid] = s; __syncthreads();
    for (int o = 128; o > 0; o >>= 1) { if (tid < o) red[tid] += red[tid + o]; __syncthreads(); }
    float mu = red[0] * (1.0f / HID);
    __syncthreads();
    float sq = 0.f;
#pragma unroll
    for (int i = 0; i < 5; i++) { float d = v[i] - mu; sq += d * d; }
    red[tid] = sq; __syncthreads();
    for (int o = 128; o > 0; o >>= 1) { if (tid < o) red[tid] += red[tid + o]; __syncthreads(); }
    float rs = rsqrtf(red[0] * (1.0f / HID) + 1e-5f);
#pragma unroll
    for (int i = 0; i < 5; i++) {
        int c = tid + i * 256;
        out[(long long)row * HID + c] = __float2half((v[i] - mu) * rs * g[c] + b[c]);
    }
}

__global__ void reshape_q_kernel(const h16* __restrict__ q, h16* __restrict__ qh) {
    long long idx = (long long)blockIdx.x * blockDim.x + threadIdx.x;
    if (idx >= (long long)NBH * TQ * HD) return;
    int d = idx & (HD - 1);
    long long r = idx >> 6;
    int t = (int)(r % TQ);
    long long bh = r / TQ;
    int h = (int)(bh % NH), b = (int)(bh / NH);
    qh[idx] = q[((long long)(b * TQ + t)) * HID + h * HD + d];
}

__global__ void reshape_k_kernel(const h16* __restrict__ k, h16* __restrict__ kh, int S, int Spad) {
    long long idx = (long long)blockIdx.x * blockDim.x + threadIdx.x;
    long long tot = (long long)NBH * Spad * HD;
    if (idx >= tot) return;
    int d = idx & (HD - 1);
    long long r = idx >> 6;
    int s = (int)(r % Spad);
    long long bh = r / Spad;
    int h = (int)(bh % NH), b = (int)(bh / NH);
    h16 val = __float2half(0.f);
    if (s < S) val = k[((long long)(b * S + s)) * HID + h * HD + d];
    kh[idx] = val;
}

__global__ void reshape_vT_kernel(const h16* __restrict__ v, h16* __restrict__ vT, int S, int Spad) {
    long long idx = (long long)blockIdx.x * blockDim.x + threadIdx.x;
    long long tot = (long long)NBH * HD * Spad;
    if (idx >= tot) return;
    int s = (int)(idx % Spad);
    long long r = idx / Spad;
    int d = (int)(r % HD);
    long long bh = r / HD;
    int h = (int)(bh % NH), b = (int)(bh / NH);
    h16 val = __float2half(0.f);
    if (s < S) val = v[((long long)(b * S + s)) * HID + h * HD + d];
    vT[idx] = val;
}

__global__ void softmax_kernel(const float* __restrict__ S, h16* __restrict__ P, int Spad, int Sval) {
    __shared__ float red[256];
    long long row = blockIdx.x;
    const float* sr = S + row * (long long)Spad;
    int tid = threadIdx.x;
    float vals[8];
    int cnt = 0;
    float mx = -1e30f;
    for (int j = tid; j < Sval; j += 256) { float v = sr[j]; vals[cnt++] = v; mx = fmaxf(mx, v); }
    red[tid] = mx; __syncthreads();
    for (int o = 128; o > 0; o >>= 1) { if (tid < o) red[tid] = fmaxf(red[tid], red[tid + o]); __syncthreads(); }
    mx = red[0]; __syncthreads();
    float sum = 0.f;
    for (int i = 0; i < cnt; i++) { vals[i] = expf(vals[i] - mx); sum += vals[i]; }
    red[tid] = sum; __syncthreads();
    for (int o = 128; o > 0; o >>= 1) { if (tid < o) red[tid] += red[tid + o]; __syncthreads(); }
    float inv = 1.f / red[0];
    h16* pr = P + row * (long long)Spad;
    cnt = 0;
    for (int j = tid; j < Spad; j += 256) {
        float o = (j < Sval) ? vals[cnt++] * inv : 0.f;
        pr[j] = __float2half(o);
    }
}

__global__ void geglu_kernel(const float* __restrict__ proj, h16* __restrict__ out) {
    long long i = (long long)blockIdx.x * blockDim.x + threadIdx.x;
    if (i >= (long long)M1 * FFD) return;
    long long r = i / FFD;
    int c = (int)(i % FFD);
    float x1 = proj[r * (2 * FFD) + c];
    float x2 = proj[r * (2 * FFD) + FFD + c];
    float gel = 0.5f * x2 * (1.0f + erff(x2 * 0.7071067811865476f));
    out[i] = __float2half(x1 * gel);
}

// ---------------- cp.async pipelined batched fp16 tensor-core GEMM ----------------
// C[z][M][N] = scale * (A[z] @ W[z]^T) + bias + residual
// A,W fp16 in gmem; C fp32 (Cf) and/or fp16 (Ch). fp32 accumulate.
// CTA tile 128x128x64, 512 threads (16 warps 4x4, warp tile 32x32).
// 4-stage cp.async pipeline, 1 barrier per k-tile, stride-88 smem (aligned + conflict-free).
__device__ __forceinline__ void mma16816(float c[4], const uint32_t a[4], const uint32_t b[2]) {
    asm volatile(
        "mma.sync.aligned.m16n8k16.row.col.f32.f16.f16.f32 "
        "{%0,%1,%2,%3}, {%4,%5,%6,%7}, {%8,%9}, {%0,%1,%2,%3};\n"
        : "+f"(c[0]), "+f"(c[1]), "+f"(c[2]), "+f"(c[3])
        : "r"(a[0]), "r"(a[1]), "r"(a[2]), "r"(a[3]), "r"(b[0]), "r"(b[1]));
}

__device__ __forceinline__ void cpasync16(uint32_t dst, const void* src, bool pred) {
    int sz = pred ? 16 : 0;
    asm volatile("cp.async.cg.shared.global [%0], [%1], 16, %2;\n"
                 :: "r"(dst), "l"(src), "r"(sz));
}
__device__ __forceinline__ void cp_commit() {
    asm volatile("cp.async.commit_group;\n" ::: "memory");
}
__device__ __forceinline__ void cp_wait2() {
    asm volatile("cp.async.wait_group 2;\n" ::: "memory");
}

#define KTILE    64
#define LDS_S    88                       /* halfs per row: 176B = 11*16, conflict-free */
#define STG_ELE  (128 * LDS_S)            /* 11264 halfs = 22528 B */
#define STAGES   4
#define SMEM_BYTES (2 * STAGES * STG_ELE * 2)  /* A + B, 4 stages: 180224 */

__global__ __launch_bounds__(512, 1) void gemm_kernel(
    const h16* __restrict__ A, const h16* __restrict__ W,
    const float* __restrict__ bias, const float* __restrict__ residual,
    float* __restrict__ Cf, h16* __restrict__ Ch,
    int M, int N, int K,
    long long aStride, long long wStride,
    long long cHi, long long cLo, int cDiv, int ldc, float scale)
{
    extern __shared__ __align__(16) h16 sm[];
    h16* sA = sm;                         // [STAGES][128][88]
    h16* sB = sm + STAGES * STG_ELE;

    int z = blockIdx.z;
    A += (long long)z * aStride;
    W += (long long)z * wStride;
    long long cOff = (long long)(z / cDiv) * cHi + (long long)(z % cDiv) * cLo;

    int tid = threadIdx.x;
    int lane = tid & 31, warp = tid >> 5;
    int wm = warp >> 2, wn = warp & 3;      // 4x4 warp grid, 32x32 warp tile
    int rowBase = blockIdx.y * 128;
    int colBase = blockIdx.x * 128;
    bool wactive = (colBase + wn * 32) < N;

    uint32_t sA_u = (uint32_t)__cvta_generic_to_shared(sA);
    uint32_t sB_u = (uint32_t)__cvta_generic_to_shared(sB);

    // copy mapping: 2 chunks of 16B per operand per thread per k-tile
    int cr[2], cc[2];
#pragma unroll
    for (int jt = 0; jt < 2; ++jt) {
        int j = tid + jt * 512;           // 0..1023
        cr[jt] = j >> 3;                  // row 0..127
        cc[jt] = (j & 7) << 3;            // half-offset 0..56
    }

    float acc[2][4][4];
#pragma unroll
    for (int i = 0; i < 2; i++)
#pragma unroll
        for (int j = 0; j < 4; j++)
#pragma unroll
            for (int l = 0; l < 4; l++) acc[i][j][l] = 0.f;

    int kTiles = K >> 6;

    // ---- issue copies for one k-tile into stage st ----
    auto issue = [&](int st, int k0) {
        uint32_t aBase = sA_u + st * (STG_ELE * 2);
        uint32_t bBase = sB_u + st * (STG_ELE * 2);
#pragma unroll
        for (int jt = 0; jt < 2; ++jt) {
            int r = cr[jt], c = cc[jt];
            uint32_t soff = (uint32_t)(r * LDS_S + c) * 2;
            int gr = rowBase + r;
            int grc = gr < M ? gr : (M - 1);
            cpasync16(aBase + soff, A + (long long)grc * K + k0 + c, gr < M);
            int gn = colBase + r;
            int gnc = gn < N ? gn : (N - 1);
            cpasync16(bBase + soff, W + (long long)gnc * K + k0 + c, gn < N);
        }
    };

    // prologue: fill STAGES-1 groups (empty commits past kTiles)
#pragma unroll
    for (int f = 0; f < STAGES - 1; ++f) {
        if (f < kTiles) issue(f, f << 6);
        cp_commit();
    }

    for (int kt = 0; kt < kTiles; ++kt) {
        cp_wait2();
        __syncthreads();
        // issue next tile (stage (kt+3)%4) or empty group to keep counts constant
        int nf = kt + STAGES - 1;
        if (nf < kTiles) issue(nf & (STAGES - 1), nf << 6);
        cp_commit();

        if (wactive) {
            const h16* Ah = sA + (kt & (STAGES - 1)) * STG_ELE;
            const h16* Bh = sB + (kt & (STAGES - 1)) * STG_ELE;
#pragma unroll
            for (int kk = 0; kk < KTILE; kk += 16) {
                uint32_t a[2][4];
#pragma unroll
                for (int mt = 0; mt < 2; ++mt) {
                    int r = wm * 32 + mt * 16 + (lane >> 2);
                    int c = kk + (lane & 3) * 2;
                    a[mt][0] = *(const uint32_t*)(Ah + r * LDS_S + c);
                    a[mt][1] = *(const uint32_t*)(Ah + (r + 8) * LDS_S + c);
                    a[mt][2] = *(const uint32_t*)(Ah + r * LDS_S + c + 8);
                    a[mt][3] = *(const uint32_t*)(Ah + (r + 8) * LDS_S + c + 8);
                }
#pragma unroll
                for (int nt = 0; nt < 4; ++nt) {
                    int n = wn * 32 + nt * 8 + (lane >> 2);
                    int c = kk + (lane & 3) * 2;
                    uint32_t b[2];
                    b[0] = *(const uint32_t*)(Bh + n * LDS_S + c);
                    b[1] = *(const uint32_t*)(Bh + n * LDS_S + c + 8);
#pragma unroll
                    for (int mt = 0; mt < 2; ++mt)
                        mma16816(acc[mt][nt], a[mt], b);
                }
            }
        }
    }

    if (wactive) {
#pragma unroll
        for (int mt = 0; mt < 2; ++mt)
#pragma unroll
            for (int nt = 0; nt < 4; ++nt) {
                int col = colBase + wn * 32 + nt * 8 + (lane & 3) * 2;
                if (col >= N) continue;
#pragma unroll
                for (int i = 0; i < 2; ++i) {
                    int row = rowBase + wm * 32 + mt * 16 + (lane >> 2) + i * 8;
                    if (row >= M) continue;
                    float v0 = acc[mt][nt][i * 2 + 0] * scale;
                    float v1 = acc[mt][nt][i * 2 + 1] * scale;
                    if (bias) { v0 += bias[col]; v1 += bias[col + 1]; }
                    long long o = cOff + (long long)row * ldc + col;
                    if (residual) { v0 += residual[o]; v1 += residual[o + 1]; }
                    if (Cf) { Cf[o] = v0; Cf[o + 1] = v1; }
                    if (Ch) { Ch[o] = __float2half(v0); Ch[o + 1] = __float2half(v1); }
                }
            }
    }
}

// ---------------- host glue ----------------
static void gemm(const h16* A, const h16* W, const float* bias, const float* res,
                 float* Cf, h16* Ch, int M, int N, int K, int Z,
                 long long aS, long long wS, long long cHi, long long cLo, int cDiv,
                 int ldc, float scale) {
    dim3 g((N + 127) / 128, (M + 127) / 128, Z);
    gemm_kernel<<<g, 512, SMEM_BYTES>>>(A, W, bias, res, Cf, Ch, M, N, K, aS, wS, cHi, cLo, cDiv, ldc, scale);
}

static void f2h(const float* in, h16* out, long long n) {
    f2h_kernel<<<(unsigned)((n + 255) / 256), 256>>>(in, out, n);
}

extern "C" void kernel_launch(void* const* d_in, const int* in_sizes, int n_in,
                              void* d_out, int out_size) {
    const float* x     = (const float*)d_in[0];
    const float* enc   = (const float*)d_in[1];
    const float* ln1g  = (const float*)d_in[2];
    const float* ln1b  = (const float*)d_in[3];
    const float* ln2g  = (const float*)d_in[4];
    const float* ln2b  = (const float*)d_in[5];
    const float* ln3g  = (const float*)d_in[6];
    const float* ln3b  = (const float*)d_in[7];
    const float* wq1   = (const float*)d_in[8];
    const float* wk1   = (const float*)d_in[9];
    const float* wv1   = (const float*)d_in[10];
    const float* wo1   = (const float*)d_in[11];
    const float* bo1   = (const float*)d_in[12];
    const float* wq2   = (const float*)d_in[13];
    const float* wk2   = (const float*)d_in[14];
    const float* wv2   = (const float*)d_in[15];
    const float* wo2   = (const float*)d_in[16];
    const float* bo2   = (const float*)d_in[17];
    const float* wgg   = (const float*)d_in[18];
    const float* bgg   = (const float*)d_in[19];
    const float* wff   = (const float*)d_in[20];
    const float* bff   = (const float*)d_in[21];
    float* out = (float*)d_out;

    static bool attr_done = false;
    if (!attr_done) {
        cudaFuncSetAttribute(gemm_kernel, cudaFuncAttributeMaxDynamicSharedMemorySize, SMEM_BYTES);
        attr_done = true;
    }

    h16 *h, *p1, *p2, *p3, *qh, *kh, *vT, *probs, *att, *ff, *encb;
    float *scores, *xcur, *proj;
    cudaGetSymbolAddress((void**)&h,      g_h);
    cudaGetSymbolAddress((void**)&p1,     g_p1);
    cudaGetSymbolAddress((void**)&p2,     g_p2);
    cudaGetSymbolAddress((void**)&p3,     g_p3);
    cudaGetSymbolAddress((void**)&qh,     g_qh);
    cudaGetSymbolAddress((void**)&kh,     g_kh);
    cudaGetSymbolAddress((void**)&vT,     g_vT);
    cudaGetSymbolAddress((void**)&scores, g_scores);
    cudaGetSymbolAddress((void**)&probs,  g_probs);
    cudaGetSymbolAddress((void**)&att,    g_att);
    cudaGetSymbolAddress((void**)&xcur,   g_x);
    cudaGetSymbolAddress((void**)&proj,   g_proj);
    cudaGetSymbolAddress((void**)&ff,     g_ff);
    cudaGetSymbolAddress((void**)&encb,   g_enc);

    h16 *Wq1, *Wk1, *Wv1, *Wo1, *Wq2, *Wk2, *Wv2, *Wo2, *Wgg, *Wff;
    cudaGetSymbolAddress((void**)&Wq1, g_wq1h);
    cudaGetSymbolAddress((void**)&Wk1, g_wk1h);
    cudaGetSymbolAddress((void**)&Wv1, g_wv1h);
    cudaGetSymbolAddress((void**)&Wo1, g_wo1h);
    cudaGetSymbolAddress((void**)&Wq2, g_wq2h);
    cudaGetSymbolAddress((void**)&Wk2, g_wk2h);
    cudaGetSymbolAddress((void**)&Wv2, g_wv2h);
    cudaGetSymbolAddress((void**)&Wo2, g_wo2h);
    cudaGetSymbolAddress((void**)&Wgg, g_wggh);
    cudaGetSymbolAddress((void**)&Wff, g_wffh);

    // weight + encoder conversion to fp16 (~30us)
    f2h(wq1, Wq1, (long long)HID * HID);
    f2h(wk1, Wk1, (long long)HID * HID);
    f2h(wv1, Wv1, (long long)HID * HID);
    f2h(wo1, Wo1, (long long)HID * HID);
    f2h(wq2, Wq2, (long long)HID * HID);
    f2h(wk2, Wk2, (long long)HID * CROSSD);
    f2h(wv2, Wv2, (long long)HID * CROSSD);
    f2h(wo2, Wo2, (long long)HID * HID);
    f2h(wgg, Wgg, (long long)2 * FFD * HID);
    f2h(wff, Wff, (long long)HID * FFD);
    f2h(enc, encb, (long long)MENC * CROSSD);

    // ---- self attention ----
    ln_kernel<<<M1, 256>>>(x, ln1g, ln1b, h);
    gemm(h, Wq1, nullptr, nullptr, nullptr, p1, M1, HID, HID, 1, 0, 0, 0, 0, 1, HID, 1.f);
    gemm(h, Wk1, nullptr, nullptr, nullptr, p2, M1, HID, HID, 1, 0, 0, 0, 0, 1, HID, 1.f);
    gemm(h, Wv1, nullptr, nullptr, nullptr, p3, M1, HID, HID, 1, 0, 0, 0, 0, 1, HID, 1.f);
    {
        long long nq = (long long)NBH * TQ * HD;
        reshape_q_kernel<<<(unsigned)((nq + 255) / 256), 256>>>(p1, qh);
        reshape_k_kernel<<<(unsigned)((nq + 255) / 256), 256>>>(p2, kh, TQ, TQ);
        reshape_vT_kernel<<<(unsigned)((nq + 255) / 256), 256>>>(p3, vT, TQ, TQ);
    }
    gemm(qh, kh, nullptr, nullptr, scores, nullptr, TQ, TQ, HD, NBH,
         (long long)TQ * HD, (long long)TQ * HD, (long long)TQ * TQ, 0, 1, TQ, 0.125f);
    softmax_kernel<<<NBH * TQ, 256>>>(scores, probs, TQ, TQ);
    gemm(probs, vT, nullptr, nullptr, nullptr, att, TQ, HD, TQ, NBH,
         (long long)TQ * TQ, (long long)HD * TQ,
         (long long)TQ * HID, (long long)HD, NH, HID, 1.f);
    gemm(att, Wo1, bo1, x, xcur, nullptr, M1, HID, HID, 1, 0, 0, 0, 0, 1, HID, 1.f);

    // ---- cross attention ----
    ln_kernel<<<M1, 256>>>(xcur, ln2g, ln2b, h);
    gemm(h, Wq2, nullptr, nullptr, nullptr, p1, M1, HID, HID, 1, 0, 0, 0, 0, 1, HID, 1.f);
    gemm(encb, Wk2, nullptr, nullptr, nullptr, p2, MENC, HID, CROSSD, 1, 0, 0, 0, 0, 1, HID, 1.f);
    gemm(encb, Wv2, nullptr, nullptr, nullptr, p3, MENC, HID, CROSSD, 1, 0, 0, 0, 0, 1, HID, 1.f);
    {
        long long nq = (long long)NBH * TQ * HD;
        long long nk = (long long)NBH * SPAD * HD;
        reshape_q_kernel<<<(unsigned)((nq + 255) / 256), 256>>>(p1, qh);
        reshape_k_kernel<<<(unsigned)((nk + 255) / 256), 256>>>(p2, kh, SENC, SPAD);
        reshape_vT_kernel<<<(unsigned)((nk + 255) / 256), 256>>>(p3, vT, SENC, SPAD);
    }
    gemm(qh, kh, nullptr, nullptr, scores, nullptr, TQ, SPAD, HD, NBH,
         (long long)TQ * HD, (long long)SPAD * HD, (long long)TQ * SPAD, 0, 1, SPAD, 0.125f);
    softmax_kernel<<<NBH * TQ, 256>>>(scores, probs, SPAD, SENC);
    gemm(probs, vT, nullptr, nullptr, nullptr, att, TQ, HD, SPAD, NBH,
         (long long)TQ * SPAD, (long long)HD * SPAD,
         (long long)TQ * HID, (long long)HD, NH, HID, 1.f);
    gemm(att, Wo2, bo2, xcur, xcur, nullptr, M1, HID, HID, 1, 0, 0, 0, 0, 1, HID, 1.f);

    // ---- GEGLU FF ----
    ln_kernel<<<M1, 256>>>(xcur, ln3g, ln3b, h);
    gemm(h, Wgg, bgg, nullptr, proj, nullptr, M1, 2 * FFD, HID, 1, 0, 0, 0, 0, 1, 2 * FFD, 1.f);
    {
        long long n = (long long)M1 * FFD;
        geglu_kernel<<<(unsigned)((n + 255) / 256), 256>>>(proj, ff);
    }
    gemm(ff, Wff, bff, xcur, out, nullptr, M1, HID, FFD, 1, 0, 0, 0, 0, 1, HID, 1.f);

    (void)in_sizes; (void)n_in; (void)out_size;
}

// round 13
// speedup vs baseline: 3.8805x; 1.3843x over previous
#include <cuda_runtime.h>
#include <cuda_fp16.h>
#include <cstdint>

#define BATCH 2
#define TQ    2048
#define HID   1280
#define NH    20
#define HD    64
#define CROSSD 2048
#define SENC  77
#define SPAD  128
#define FFD   5120
#define M1    (BATCH*TQ)     /* 4096 */
#define MENC  (BATCH*SENC)   /* 154  */
#define NBH   (BATCH*NH)     /* 40   */

typedef __half h16;

// ---------------- scratch (device globals; no allocation) ----------------
__device__ h16   g_h   [M1*HID];
__device__ h16   g_p1  [M1*HID];
__device__ h16   g_p2  [M1*HID];
__device__ h16   g_p3  [M1*HID];
__device__ h16   g_qh  [(size_t)NBH*TQ*HD];
__device__ h16   g_kh  [(size_t)NBH*TQ*HD];
__device__ h16   g_vT  [(size_t)NBH*HD*TQ];
__device__ h16   g_att [M1*HID];
__device__ float g_x   [M1*HID];
__device__ float g_proj[(size_t)M1*2*FFD];
__device__ h16   g_ff  [(size_t)M1*FFD];
__device__ h16   g_enc [MENC*CROSSD];
// fp16 weights
__device__ h16 g_wq1h[HID*HID];
__device__ h16 g_wk1h[HID*HID];
__device__ h16 g_wv1h[HID*HID];
__device__ h16 g_wo1h[HID*HID];
__device__ h16 g_wq2h[HID*HID];
__device__ h16 g_wk2h[HID*CROSSD];
__device__ h16 g_wv2h[HID*CROSSD];
__device__ h16 g_wo2h[HID*HID];
__device__ h16 g_wggh[2*FFD*HID];
__device__ h16 g_wffh[HID*FFD];

// ---------------- elementwise kernels ----------------
__global__ void f2h_kernel(const float* __restrict__ in, h16* __restrict__ out, long long n) {
    long long i = (long long)blockIdx.x * blockDim.x + threadIdx.x;
    if (i < n) out[i] = __float2half(in[i]);
}

__global__ void ln_kernel(const float* __restrict__ x, const float* __restrict__ g,
                          const float* __restrict__ b, h16* __restrict__ out) {
    __shared__ float red[256];
    int row = blockIdx.x, tid = threadIdx.x;
    const float* xr = x + (long long)row * HID;
    float v[5], s = 0.f;
#pragma unroll
    for (int i = 0; i < 5; i++) { v[i] = xr[tid + i * 256]; s += v[i]; }
    red[tid] = s; __syncthreads();
    for (int o = 128; o > 0; o >>= 1) { if (tid < o) red[tid] += red[tid + o]; __syncthreads(); }
    float mu = red[0] * (1.0f / HID);
    __syncthreads();
    float sq = 0.f;
#pragma unroll
    for (int i = 0; i < 5; i++) { float d = v[i] - mu; sq += d * d; }
    red[tid] = sq; __syncthreads();
    for (int o = 128; o > 0; o >>= 1) { if (tid < o) red[tid] += red[tid + o]; __syncthreads(); }
    float rs = rsqrtf(red[0] * (1.0f / HID) + 1e-5f);
#pragma unroll
    for (int i = 0; i < 5; i++) {
        int c = tid + i * 256;
        out[(long long)row * HID + c] = __float2half((v[i] - mu) * rs * g[c] + b[c]);
    }
}

// q: [b*t][HID] -> [bh][t][d], with softmax scale 1/8 folded in (exact in fp16)
__global__ void reshape_q_kernel(const h16* __restrict__ q, h16* __restrict__ qh) {
    long long idx = (long long)blockIdx.x * blockDim.x + threadIdx.x;
    if (idx >= (long long)NBH * TQ * HD) return;
    int d = idx & (HD - 1);
    long long r = idx >> 6;
    int t = (int)(r % TQ);
    long long bh = r / TQ;
    int h = (int)(bh % NH), b = (int)(bh / NH);
    float v = __half2float(q[((long long)(b * TQ + t)) * HID + h * HD + d]);
    qh[idx] = __float2half(v * 0.125f);
}

__global__ void reshape_k_kernel(const h16* __restrict__ k, h16* __restrict__ kh, int S, int Spad) {
    long long idx = (long long)blockIdx.x * blockDim.x + threadIdx.x;
    long long tot = (long long)NBH * Spad * HD;
    if (idx >= tot) return;
    int d = idx & (HD - 1);
    long long r = idx >> 6;
    int s = (int)(r % Spad);
    long long bh = r / Spad;
    int h = (int)(bh % NH), b = (int)(bh / NH);
    h16 val = __float2half(0.f);
    if (s < S) val = k[((long long)(b * S + s)) * HID + h * HD + d];
    kh[idx] = val;
}

__global__ void reshape_vT_kernel(const h16* __restrict__ v, h16* __restrict__ vT, int S, int Spad) {
    long long idx = (long long)blockIdx.x * blockDim.x + threadIdx.x;
    long long tot = (long long)NBH * HD * Spad;
    if (idx >= tot) return;
    int s = (int)(idx % Spad);
    long long r = idx / Spad;
    int d = (int)(r % HD);
    long long bh = r / HD;
    int h = (int)(bh % NH), b = (int)(bh / NH);
    h16 val = __float2half(0.f);
    if (s < S) val = v[((long long)(b * S + s)) * HID + h * HD + d];
    vT[idx] = val;
}

__global__ void geglu_kernel(const float* __restrict__ proj, h16* __restrict__ out) {
    long long i = (long long)blockIdx.x * blockDim.x + threadIdx.x;
    if (i >= (long long)M1 * FFD) return;
    long long r = i / FFD;
    int c = (int)(i % FFD);
    float x1 = proj[r * (2 * FFD) + c];
    float x2 = proj[r * (2 * FFD) + FFD + c];
    float gel = 0.5f * x2 * (1.0f + erff(x2 * 0.7071067811865476f));
    out[i] = __float2half(x1 * gel);
}

// ---------------- common asm helpers ----------------
__device__ __forceinline__ void mma16816(float c[4], const uint32_t a[4], const uint32_t b[2]) {
    asm volatile(
        "mma.sync.aligned.m16n8k16.row.col.f32.f16.f16.f32 "
        "{%0,%1,%2,%3}, {%4,%5,%6,%7}, {%8,%9}, {%0,%1,%2,%3};\n"
        : "+f"(c[0]), "+f"(c[1]), "+f"(c[2]), "+f"(c[3])
        : "r"(a[0]), "r"(a[1]), "r"(a[2]), "r"(a[3]), "r"(b[0]), "r"(b[1]));
}
__device__ __forceinline__ void cpasync16(uint32_t dst, const void* src, bool pred) {
    int sz = pred ? 16 : 0;
    asm volatile("cp.async.cg.shared.global [%0], [%1], 16, %2;\n"
                 :: "r"(dst), "l"(src), "r"(sz));
}
__device__ __forceinline__ void cp_commit() {
    asm volatile("cp.async.commit_group;\n" ::: "memory");
}
__device__ __forceinline__ void cp_wait0() { asm volatile("cp.async.wait_group 0;\n" ::: "memory"); }
__device__ __forceinline__ void cp_wait1() { asm volatile("cp.async.wait_group 1;\n" ::: "memory"); }
__device__ __forceinline__ void cp_wait2() { asm volatile("cp.async.wait_group 2;\n" ::: "memory"); }
__device__ __forceinline__ uint32_t h2u(__half2 v) { return *reinterpret_cast<uint32_t*>(&v); }
__device__ __forceinline__ uint32_t pack_h2(float a, float b) {
    __half2 v = __floats2half2_rn(a, b);
    return *reinterpret_cast<uint32_t*>(&v);
}

// ---------------- cp.async pipelined batched fp16 GEMM ----------------
#define KTILE    64
#define LDS_S    88
#define STG_ELE  (128 * LDS_S)
#define STAGES   4
#define SMEM_BYTES (2 * STAGES * STG_ELE * 2)

__global__ __launch_bounds__(512, 1) void gemm_kernel(
    const h16* __restrict__ A, const h16* __restrict__ W,
    const float* __restrict__ bias, const float* __restrict__ residual,
    float* __restrict__ Cf, h16* __restrict__ Ch,
    int M, int N, int K,
    long long aStride, long long wStride,
    long long cHi, long long cLo, int cDiv, int ldc, float scale)
{
    extern __shared__ __align__(16) h16 sm[];
    h16* sA = sm;
    h16* sB = sm + STAGES * STG_ELE;

    int z = blockIdx.z;
    A += (long long)z * aStride;
    W += (long long)z * wStride;
    long long cOff = (long long)(z / cDiv) * cHi + (long long)(z % cDiv) * cLo;

    int tid = threadIdx.x;
    int lane = tid & 31, warp = tid >> 5;
    int wm = warp >> 2, wn = warp & 3;
    int rowBase = blockIdx.y * 128;
    int colBase = blockIdx.x * 128;
    bool wactive = (colBase + wn * 32) < N;

    uint32_t sA_u = (uint32_t)__cvta_generic_to_shared(sA);
    uint32_t sB_u = (uint32_t)__cvta_generic_to_shared(sB);

    int cr[2], cc[2];
#pragma unroll
    for (int jt = 0; jt < 2; ++jt) {
        int j = tid + jt * 512;
        cr[jt] = j >> 3;
        cc[jt] = (j & 7) << 3;
    }

    float acc[2][4][4];
#pragma unroll
    for (int i = 0; i < 2; i++)
#pragma unroll
        for (int j = 0; j < 4; j++)
#pragma unroll
            for (int l = 0; l < 4; l++) acc[i][j][l] = 0.f;

    int kTiles = K >> 6;

    auto issue = [&](int st, int k0) {
        uint32_t aBase = sA_u + st * (STG_ELE * 2);
        uint32_t bBase = sB_u + st * (STG_ELE * 2);
#pragma unroll
        for (int jt = 0; jt < 2; ++jt) {
            int r = cr[jt], c = cc[jt];
            uint32_t soff = (uint32_t)(r * LDS_S + c) * 2;
            int gr = rowBase + r;
            int grc = gr < M ? gr : (M - 1);
            cpasync16(aBase + soff, A + (long long)grc * K + k0 + c, gr < M);
            int gn = colBase + r;
            int gnc = gn < N ? gn : (N - 1);
            cpasync16(bBase + soff, W + (long long)gnc * K + k0 + c, gn < N);
        }
    };

#pragma unroll
    for (int f = 0; f < STAGES - 1; ++f) {
        if (f < kTiles) issue(f, f << 6);
        cp_commit();
    }

    for (int kt = 0; kt < kTiles; ++kt) {
        cp_wait2();
        __syncthreads();
        int nf = kt + STAGES - 1;
        if (nf < kTiles) issue(nf & (STAGES - 1), nf << 6);
        cp_commit();

        if (wactive) {
            const h16* Ah = sA + (kt & (STAGES - 1)) * STG_ELE;
            const h16* Bh = sB + (kt & (STAGES - 1)) * STG_ELE;
#pragma unroll
            for (int kk = 0; kk < KTILE; kk += 16) {
                uint32_t a[2][4];
#pragma unroll
                for (int mt = 0; mt < 2; ++mt) {
                    int r = wm * 32 + mt * 16 + (lane >> 2);
                    int c = kk + (lane & 3) * 2;
                    a[mt][0] = *(const uint32_t*)(Ah + r * LDS_S + c);
                    a[mt][1] = *(const uint32_t*)(Ah + (r + 8) * LDS_S + c);
                    a[mt][2] = *(const uint32_t*)(Ah + r * LDS_S + c + 8);
                    a[mt][3] = *(const uint32_t*)(Ah + (r + 8) * LDS_S + c + 8);
                }
#pragma unroll
                for (int nt = 0; nt < 4; ++nt) {
                    int n = wn * 32 + nt * 8 + (lane >> 2);
                    int c = kk + (lane & 3) * 2;
                    uint32_t b[2];
                    b[0] = *(const uint32_t*)(Bh + n * LDS_S + c);
                    b[1] = *(const uint32_t*)(Bh + n * LDS_S + c + 8);
#pragma unroll
                    for (int mt = 0; mt < 2; ++mt)
                        mma16816(acc[mt][nt], a[mt], b);
                }
            }
        }
    }

    if (wactive) {
#pragma unroll
        for (int mt = 0; mt < 2; ++mt)
#pragma unroll
            for (int nt = 0; nt < 4; ++nt) {
                int col = colBase + wn * 32 + nt * 8 + (lane & 3) * 2;
                if (col >= N) continue;
#pragma unroll
                for (int i = 0; i < 2; ++i) {
                    int row = rowBase + wm * 32 + mt * 16 + (lane >> 2) + i * 8;
                    if (row >= M) continue;
                    float v0 = acc[mt][nt][i * 2 + 0] * scale;
                    float v1 = acc[mt][nt][i * 2 + 1] * scale;
                    if (bias) { v0 += bias[col]; v1 += bias[col + 1]; }
                    long long o = cOff + (long long)row * ldc + col;
                    if (residual) { v0 += residual[o]; v1 += residual[o + 1]; }
                    if (Cf) { Cf[o] = v0; Cf[o + 1] = v1; }
                    if (Ch) { Ch[o] = __float2half(v0); Ch[o + 1] = __float2half(v1); }
                }
            }
    }
}

// ---------------- fused flash attention ----------------
// grid (TQ/128, NBH), 256 threads (8 warps, 16 q-rows each).
// qh [bh][t][64] (pre-scaled by 1/8), kh [bh][Stot][64], vT [bh][64][Stot].
// out att[b*TQ+t][HID] at col h*64 (fp16).
// Online softmax in registers; P->PV via in-register fragment repack.
#define FKSTR 72      /* Q/K smem row stride (halfs): conflict-free */
#define FVSTR 136     /* VT smem row stride (halfs): conflict-free */
#define FQ_ELE (128 * FKSTR)
#define FK_ELE (128 * FKSTR)
#define FV_ELE (64 * FVSTR)
#define FSMEM_BYTES ((FQ_ELE + 2 * FK_ELE + 2 * FV_ELE) * 2)   /* 90112 */

__global__ __launch_bounds__(256, 1) void flash_kernel(
    const h16* __restrict__ qh, const h16* __restrict__ kh, const h16* __restrict__ vT,
    h16* __restrict__ att, int Stot, int Sval)
{
    extern __shared__ __align__(16) h16 fsm[];
    h16* sQ = fsm;
    h16* sK = fsm + FQ_ELE;               // [2][128][FKSTR]
    h16* sV = fsm + FQ_ELE + 2 * FK_ELE;  // [2][64][FVSTR]

    int tid = threadIdx.x;
    int lane = tid & 31, warp = tid >> 5;
    int l4 = lane & 3, ln4 = lane >> 2;
    int bh = blockIdx.y;
    int b = bh / NH, h = bh % NH;
    int qrow0 = blockIdx.x * 128;

    const h16* Qb = qh + (long long)bh * TQ * HD + (long long)qrow0 * HD;
    const h16* Kb = kh + (long long)bh * Stot * HD;
    const h16* Vb = vT + (long long)bh * HD * Stot;

    uint32_t sQ_u = (uint32_t)__cvta_generic_to_shared(sQ);
    uint32_t sK_u = (uint32_t)__cvta_generic_to_shared(sK);
    uint32_t sV_u = (uint32_t)__cvta_generic_to_shared(sV);

    int nk = Stot >> 7;

    // Q: 128 rows x 64 halfs = 1024 16B-chunks, 4/thread
#pragma unroll
    for (int t = 0; t < 4; ++t) {
        int i = tid + t * 256;
        int r = i >> 3, c = (i & 7) << 3;
        cpasync16(sQ_u + (uint32_t)(r * FKSTR + c) * 2, Qb + r * HD + c, true);
    }
    cp_commit();

    auto issueKV = [&](int st, int kt) {
        uint32_t kb = sK_u + st * (FK_ELE * 2);
        uint32_t vb = sV_u + st * (FV_ELE * 2);
#pragma unroll
        for (int t = 0; t < 4; ++t) {
            int i = tid + t * 256;
            int r = i >> 3, c = (i & 7) << 3;
            cpasync16(kb + (uint32_t)(r * FKSTR + c) * 2, Kb + (long long)(kt * 128 + r) * HD + c, true);
            int vr = i >> 4, vc = (i & 15) << 3;
            cpasync16(vb + (uint32_t)(vr * FVSTR + vc) * 2, Vb + (long long)vr * Stot + kt * 128 + vc, true);
        }
    };
    issueKV(0, 0);
    cp_commit();

    cp_wait1();   // Q ready
    __syncthreads();

    // Q fragments: 16 rows per warp, 4 k-steps
    uint32_t qa[4][4];
    {
        const h16* Qw = sQ + (warp * 16) * FKSTR;
#pragma unroll
        for (int kk = 0; kk < 4; ++kk) {
            int c = kk * 16 + l4 * 2;
            qa[kk][0] = *(const uint32_t*)(Qw + ln4 * FKSTR + c);
            qa[kk][1] = *(const uint32_t*)(Qw + (ln4 + 8) * FKSTR + c);
            qa[kk][2] = *(const uint32_t*)(Qw + ln4 * FKSTR + c + 8);
            qa[kk][3] = *(const uint32_t*)(Qw + (ln4 + 8) * FKSTR + c + 8);
        }
    }

    float m0 = -1e30f, m1 = -1e30f, le0 = 0.f, le1 = 0.f;
    float oc[8][4];
#pragma unroll
    for (int n = 0; n < 8; ++n)
#pragma unroll
        for (int c = 0; c < 4; ++c) oc[n][c] = 0.f;

    bool doMask = (Sval < Stot);

    for (int kt = 0; kt < nk; ++kt) {
        if (kt + 1 < nk) { issueKV((kt + 1) & 1, kt + 1); cp_commit(); cp_wait1(); }
        else cp_wait0();
        __syncthreads();

        const h16* Kt = sK + (kt & 1) * FK_ELE;
        const h16* Vt = sV + (kt & 1) * FV_ELE;

        // S = Q @ K^T : per-warp 16x128 (scale folded into Q)
        float sc[16][4];
#pragma unroll
        for (int j = 0; j < 16; ++j)
#pragma unroll
            for (int c = 0; c < 4; ++c) sc[j][c] = 0.f;
#pragma unroll
        for (int kk = 0; kk < 4; ++kk) {
#pragma unroll
            for (int j = 0; j < 16; ++j) {
                uint32_t kb2[2];
                const h16* kp = Kt + (j * 8 + ln4) * FKSTR + kk * 16 + l4 * 2;
                kb2[0] = *(const uint32_t*)(kp);
                kb2[1] = *(const uint32_t*)(kp + 8);
                mma16816(sc[j], qa[kk], kb2);
            }
        }

        // mask invalid key columns (cross attention)
        if (doMask) {
            int base = kt * 128 + l4 * 2;
#pragma unroll
            for (int j = 0; j < 16; ++j) {
                int col = base + j * 8;
                if (col >= Sval)     { sc[j][0] = -1e30f; sc[j][2] = -1e30f; }
                if (col + 1 >= Sval) { sc[j][1] = -1e30f; sc[j][3] = -1e30f; }
            }
        }

        // online softmax
        float mr0 = -1e30f, mr1 = -1e30f;
#pragma unroll
        for (int j = 0; j < 16; ++j) {
            mr0 = fmaxf(mr0, fmaxf(sc[j][0], sc[j][1]));
            mr1 = fmaxf(mr1, fmaxf(sc[j][2], sc[j][3]));
        }
        mr0 = fmaxf(mr0, __shfl_xor_sync(0xffffffffu, mr0, 1));
        mr0 = fmaxf(mr0, __shfl_xor_sync(0xffffffffu, mr0, 2));
        mr1 = fmaxf(mr1, __shfl_xor_sync(0xffffffffu, mr1, 1));
        mr1 = fmaxf(mr1, __shfl_xor_sync(0xffffffffu, mr1, 2));
        float mn0 = fmaxf(m0, mr0), mn1 = fmaxf(m1, mr1);
        float a0 = expf(m0 - mn0), a1 = expf(m1 - mn1);
        float s0 = 0.f, s1 = 0.f;
#pragma unroll
        for (int j = 0; j < 16; ++j) {
            sc[j][0] = expf(sc[j][0] - mn0);
            sc[j][1] = expf(sc[j][1] - mn0);
            sc[j][2] = expf(sc[j][2] - mn1);
            sc[j][3] = expf(sc[j][3] - mn1);
            s0 += sc[j][0] + sc[j][1];
            s1 += sc[j][2] + sc[j][3];
        }
        s0 += __shfl_xor_sync(0xffffffffu, s0, 1);
        s0 += __shfl_xor_sync(0xffffffffu, s0, 2);
        s1 += __shfl_xor_sync(0xffffffffu, s1, 1);
        s1 += __shfl_xor_sync(0xffffffffu, s1, 2);
        le0 = a0 * le0 + s0;
        le1 = a1 * le1 + s1;
        m0 = mn0; m1 = mn1;
#pragma unroll
        for (int n = 0; n < 8; ++n) {
            oc[n][0] *= a0; oc[n][1] *= a0;
            oc[n][2] *= a1; oc[n][3] *= a1;
        }

        // O += P @ V  (P packed in-register from S accumulators)
#pragma unroll
        for (int kk = 0; kk < 8; ++kk) {
            int j0 = kk * 2, j1 = kk * 2 + 1;
            uint32_t pa[4];
            pa[0] = pack_h2(sc[j0][0], sc[j0][1]);
            pa[1] = pack_h2(sc[j0][2], sc[j0][3]);
            pa[2] = pack_h2(sc[j1][0], sc[j1][1]);
            pa[3] = pack_h2(sc[j1][2], sc[j1][3]);
#pragma unroll
            for (int n = 0; n < 8; ++n) {
                uint32_t vb2[2];
                const h16* vp = Vt + (n * 8 + ln4) * FVSTR + kk * 16 + l4 * 2;
                vb2[0] = *(const uint32_t*)(vp);
                vb2[1] = *(const uint32_t*)(vp + 8);
                mma16816(oc[n], pa, vb2);
            }
        }
        __syncthreads();
    }

    // epilogue: normalize + store fp16 into att at head offset
    float il0 = 1.f / le0, il1 = 1.f / le1;
    int r0 = qrow0 + warp * 16 + ln4;
    int r1 = r0 + 8;
    long long o0 = ((long long)(b * TQ) + r0) * HID + h * HD;
    long long o1 = ((long long)(b * TQ) + r1) * HID + h * HD;
#pragma unroll
    for (int n = 0; n < 8; ++n) {
        int d = n * 8 + l4 * 2;
        uint32_t v0 = pack_h2(oc[n][0] * il0, oc[n][1] * il0);
        uint32_t v1 = pack_h2(oc[n][2] * il1, oc[n][3] * il1);
        *(uint32_t*)(att + o0 + d) = v0;
        *(uint32_t*)(att + o1 + d) = v1;
    }
}

// ---------------- host glue ----------------
static void gemm(const h16* A, const h16* W, const float* bias, const float* res,
                 float* Cf, h16* Ch, int M, int N, int K, int Z,
                 long long aS, long long wS, long long cHi, long long cLo, int cDiv,
                 int ldc, float scale) {
    dim3 g((N + 127) / 128, (M + 127) / 128, Z);
    gemm_kernel<<<g, 512, SMEM_BYTES>>>(A, W, bias, res, Cf, Ch, M, N, K, aS, wS, cHi, cLo, cDiv, ldc, scale);
}

static void f2h(const float* in, h16* out, long long n) {
    f2h_kernel<<<(unsigned)((n + 255) / 256), 256>>>(in, out, n);
}

extern "C" void kernel_launch(void* const* d_in, const int* in_sizes, int n_in,
                              void* d_out, int out_size) {
    const float* x     = (const float*)d_in[0];
    const float* enc   = (const float*)d_in[1];
    const float* ln1g  = (const float*)d_in[2];
    const float* ln1b  = (const float*)d_in[3];
    const float* ln2g  = (const float*)d_in[4];
    const float* ln2b  = (const float*)d_in[5];
    const float* ln3g  = (const float*)d_in[6];
    const float* ln3b  = (const float*)d_in[7];
    const float* wq1   = (const float*)d_in[8];
    const float* wk1   = (const float*)d_in[9];
    const float* wv1   = (const float*)d_in[10];
    const float* wo1   = (const float*)d_in[11];
    const float* bo1   = (const float*)d_in[12];
    const float* wq2   = (const float*)d_in[13];
    const float* wk2   = (const float*)d_in[14];
    const float* wv2   = (const float*)d_in[15];
    const float* wo2   = (const float*)d_in[16];
    const float* bo2   = (const float*)d_in[17];
    const float* wgg   = (const float*)d_in[18];
    const float* bgg   = (const float*)d_in[19];
    const float* wff   = (const float*)d_in[20];
    const float* bff   = (const float*)d_in[21];
    float* out = (float*)d_out;

    static bool attr_done = false;
    if (!attr_done) {
        cudaFuncSetAttribute(gemm_kernel, cudaFuncAttributeMaxDynamicSharedMemorySize, SMEM_BYTES);
        cudaFuncSetAttribute(flash_kernel, cudaFuncAttributeMaxDynamicSharedMemorySize, FSMEM_BYTES);
        attr_done = true;
    }

    h16 *h, *p1, *p2, *p3, *qh, *kh, *vT, *att, *ff, *encb;
    float *xcur, *proj;
    cudaGetSymbolAddress((void**)&h,      g_h);
    cudaGetSymbolAddress((void**)&p1,     g_p1);
    cudaGetSymbolAddress((void**)&p2,     g_p2);
    cudaGetSymbolAddress((void**)&p3,     g_p3);
    cudaGetSymbolAddress((void**)&qh,     g_qh);
    cudaGetSymbolAddress((void**)&kh,     g_kh);
    cudaGetSymbolAddress((void**)&vT,     g_vT);
    cudaGetSymbolAddress((void**)&att,    g_att);
    cudaGetSymbolAddress((void**)&xcur,   g_x);
    cudaGetSymbolAddress((void**)&proj,   g_proj);
    cudaGetSymbolAddress((void**)&ff,     g_ff);
    cudaGetSymbolAddress((void**)&encb,   g_enc);

    h16 *Wq1, *Wk1, *Wv1, *Wo1, *Wq2, *Wk2, *Wv2, *Wo2, *Wgg, *Wff;
    cudaGetSymbolAddress((void**)&Wq1, g_wq1h);
    cudaGetSymbolAddress((void**)&Wk1, g_wk1h);
    cudaGetSymbolAddress((void**)&Wv1, g_wv1h);
    cudaGetSymbolAddress((void**)&Wo1, g_wo1h);
    cudaGetSymbolAddress((void**)&Wq2, g_wq2h);
    cudaGetSymbolAddress((void**)&Wk2, g_wk2h);
    cudaGetSymbolAddress((void**)&Wv2, g_wv2h);
    cudaGetSymbolAddress((void**)&Wo2, g_wo2h);
    cudaGetSymbolAddress((void**)&Wgg, g_wggh);
    cudaGetSymbolAddress((void**)&Wff, g_wffh);

    // weight + encoder conversion to fp16
    f2h(wq1, Wq1, (long long)HID * HID);
    f2h(wk1, Wk1, (long long)HID * HID);
    f2h(wv1, Wv1, (long long)HID * HID);
    f2h(wo1, Wo1, (long long)HID * HID);
    f2h(wq2, Wq2, (long long)HID * HID);
    f2h(wk2, Wk2, (long long)HID * CROSSD);
    f2h(wv2, Wv2, (long long)HID * CROSSD);
    f2h(wo2, Wo2, (long long)HID * HID);
    f2h(wgg, Wgg, (long long)2 * FFD * HID);
    f2h(wff, Wff, (long long)HID * FFD);
    f2h(enc, encb, (long long)MENC * CROSSD);

    // ---- self attention ----
    ln_kernel<<<M1, 256>>>(x, ln1g, ln1b, h);
    gemm(h, Wq1, nullptr, nullptr, nullptr, p1, M1, HID, HID, 1, 0, 0, 0, 0, 1, HID, 1.f);
    gemm(h, Wk1, nullptr, nullptr, nullptr, p2, M1, HID, HID, 1, 0, 0, 0, 0, 1, HID, 1.f);
    gemm(h, Wv1, nullptr, nullptr, nullptr, p3, M1, HID, HID, 1, 0, 0, 0, 0, 1, HID, 1.f);
    {
        long long nq = (long long)NBH * TQ * HD;
        reshape_q_kernel<<<(unsigned)((nq + 255) / 256), 256>>>(p1, qh);
        reshape_k_kernel<<<(unsigned)((nq + 255) / 256), 256>>>(p2, kh, TQ, TQ);
        reshape_vT_kernel<<<(unsigned)((nq + 255) / 256), 256>>>(p3, vT, TQ, TQ);
    }
    flash_kernel<<<dim3(TQ / 128, NBH), 256, FSMEM_BYTES>>>(qh, kh, vT, att, TQ, TQ);
    gemm(att, Wo1, bo1, x, xcur, nullptr, M1, HID, HID, 1, 0, 0, 0, 0, 1, HID, 1.f);

    // ---- cross attention ----
    ln_kernel<<<M1, 256>>>(xcur, ln2g, ln2b, h);
    gemm(h, Wq2, nullptr, nullptr, nullptr, p1, M1, HID, HID, 1, 0, 0, 0, 0, 1, HID, 1.f);
    gemm(encb, Wk2, nullptr, nullptr, nullptr, p2, MENC, HID, CROSSD, 1, 0, 0, 0, 0, 1, HID, 1.f);
    gemm(encb, Wv2, nullptr, nullptr, nullptr, p3, MENC, HID, CROSSD, 1, 0, 0, 0, 0, 1, HID, 1.f);
    {
        long long nq = (long long)NBH * TQ * HD;
        long long nk = (long long)NBH * SPAD * HD;
        reshape_q_kernel<<<(unsigned)((nq + 255) / 256), 256>>>(p1, qh);
        reshape_k_kernel<<<(unsigned)((nk + 255) / 256), 256>>>(p2, kh, SENC, SPAD);
        reshape_vT_kernel<<<(unsigned)((nk + 255) / 256), 256>>>(p3, vT, SENC, SPAD);
    }
    flash_kernel<<<dim3(TQ / 128, NBH), 256, FSMEM_BYTES>>>(qh, kh, vT, att, SPAD, SENC);
    gemm(att, Wo2, bo2, xcur, xcur, nullptr, M1, HID, HID, 1, 0, 0, 0, 0, 1, HID, 1.f);

    // ---- GEGLU FF ----
    ln_kernel<<<M1, 256>>>(xcur, ln3g, ln3b, h);
    gemm(h, Wgg, bgg, nullptr, proj, nullptr, M1, 2 * FFD, HID, 1, 0, 0, 0, 0, 1, 2 * FFD, 1.f);
    {
        long long n = (long long)M1 * FFD;
        geglu_kernel<<<(unsigned)((n + 255) / 256), 256>>>(proj, ff);
    }
    gemm(ff, Wff, bff, xcur, out, nullptr, M1, HID, FFD, 1, 0, 0, 0, 0, 1, HID, 1.f);

    (void)in_sizes; (void)n_in; (void)out_size;
}

// round 14
// speedup vs baseline: 4.2544x; 1.0964x over previous
#include <cuda_runtime.h>
#include <cuda_fp16.h>
#include <cstdint>

#define BATCH 2
#define TQ    2048
#define HID   1280
#define NH    20
#define HD    64
#define CROSSD 2048
#define SENC  77
#define SPAD  128
#define FFD   5120
#define M1    (BATCH*TQ)     /* 4096 */
#define MENC  (BATCH*SENC)   /* 154  */
#define NBH   (BATCH*NH)     /* 40   */

typedef __half h16;

// ---------------- scratch (device globals; no allocation) ----------------
__device__ h16   g_h    [M1*HID];
__device__ h16   g_pqkv [(size_t)M1*3*HID];
__device__ h16   g_pq   [M1*HID];
__device__ h16   g_pkv  [MENC*2*HID];
__device__ h16   g_qh   [(size_t)NBH*TQ*HD];
__device__ h16   g_kh   [(size_t)NBH*TQ*HD];
__device__ h16   g_vT   [(size_t)NBH*HD*TQ];
__device__ h16   g_att  [M1*HID];
__device__ float g_x    [M1*HID];
__device__ h16   g_ff   [(size_t)M1*FFD];
__device__ h16   g_enc  [MENC*CROSSD];
// fp16 weights
__device__ h16   g_wqkv1h[3*HID*HID];
__device__ h16   g_wo1h[HID*HID];
__device__ h16   g_wq2h[HID*HID];
__device__ h16   g_wkv2h[2*HID*CROSSD];
__device__ h16   g_wo2h[HID*HID];
__device__ h16   g_wggh[2*FFD*HID];    // permuted: row 2c = orig c, row 2c+1 = orig FFD+c
__device__ float g_bggp[2*FFD];        // permuted bias
__device__ h16   g_wffh[HID*FFD];

// ---------------- elementwise kernels ----------------
__global__ void f2h_kernel(const float* __restrict__ in, h16* __restrict__ out, long long n) {
    long long i = (long long)blockIdx.x * blockDim.x + threadIdx.x;
    if (i < n) out[i] = __float2half(in[i]);
}

// permute w_geglu rows: out row 2c = src row c, out row 2c+1 = src row FFD+c
__global__ void permute_wgg_kernel(const float* __restrict__ in, h16* __restrict__ out) {
    long long i = (long long)blockIdx.x * blockDim.x + threadIdx.x;
    if (i >= (long long)2 * FFD * HID) return;
    int k = (int)(i % HID);
    int r = (int)(i / HID);
    int c = r >> 1;
    int srcRow = (r & 1) ? (FFD + c) : c;
    out[i] = __float2half(in[(long long)srcRow * HID + k]);
}

__global__ void permute_bgg_kernel(const float* __restrict__ in, float* __restrict__ out) {
    int i = blockIdx.x * blockDim.x + threadIdx.x;
    if (i >= 2 * FFD) return;
    int c = i >> 1;
    out[i] = in[(i & 1) ? (FFD + c) : c];
}

__global__ void ln_kernel(const float* __restrict__ x, const float* __restrict__ g,
                          const float* __restrict__ b, h16* __restrict__ out) {
    __shared__ float red[256];
    int row = blockIdx.x, tid = threadIdx.x;
    const float* xr = x + (long long)row * HID;
    float v[5], s = 0.f;
#pragma unroll
    for (int i = 0; i < 5; i++) { v[i] = xr[tid + i * 256]; s += v[i]; }
    red[tid] = s; __syncthreads();
    for (int o = 128; o > 0; o >>= 1) { if (tid < o) red[tid] += red[tid + o]; __syncthreads(); }
    float mu = red[0] * (1.0f / HID);
    __syncthreads();
    float sq = 0.f;
#pragma unroll
    for (int i = 0; i < 5; i++) { float d = v[i] - mu; sq += d * d; }
    red[tid] = sq; __syncthreads();
    for (int o = 128; o > 0; o >>= 1) { if (tid < o) red[tid] += red[tid + o]; __syncthreads(); }
    float rs = rsqrtf(red[0] * (1.0f / HID) + 1e-5f);
#pragma unroll
    for (int i = 0; i < 5; i++) {
        int c = tid + i * 256;
        out[(long long)row * HID + c] = __float2half((v[i] - mu) * rs * g[c] + b[c]);
    }
}

// q: src [b*t][stride] col h*64+d -> [bh][t][d], scaled by 1/8
__global__ void reshape_q_kernel(const h16* __restrict__ q, h16* __restrict__ qh,
                                 int stride, int colOff) {
    long long idx = (long long)blockIdx.x * blockDim.x + threadIdx.x;
    if (idx >= (long long)NBH * TQ * HD) return;
    int d = idx & (HD - 1);
    long long r = idx >> 6;
    int t = (int)(r % TQ);
    long long bh = r / TQ;
    int h = (int)(bh % NH), b = (int)(bh / NH);
    float v = __half2float(q[((long long)(b * TQ + t)) * stride + colOff + h * HD + d]);
    qh[idx] = __float2half(v * 0.125f);
}

__global__ void reshape_k_kernel(const h16* __restrict__ k, h16* __restrict__ kh,
                                 int S, int Spad, int stride, int colOff) {
    long long idx = (long long)blockIdx.x * blockDim.x + threadIdx.x;
    long long tot = (long long)NBH * Spad * HD;
    if (idx >= tot) return;
    int d = idx & (HD - 1);
    long long r = idx >> 6;
    int s = (int)(r % Spad);
    long long bh = r / Spad;
    int h = (int)(bh % NH), b = (int)(bh / NH);
    h16 val = __float2half(0.f);
    if (s < S) val = k[((long long)(b * S + s)) * stride + colOff + h * HD + d];
    kh[idx] = val;
}

__global__ void reshape_vT_kernel(const h16* __restrict__ v, h16* __restrict__ vT,
                                  int S, int Spad, int stride, int colOff) {
    long long idx = (long long)blockIdx.x * blockDim.x + threadIdx.x;
    long long tot = (long long)NBH * HD * Spad;
    if (idx >= tot) return;
    int s = (int)(idx % Spad);
    long long r = idx / Spad;
    int d = (int)(r % HD);
    long long bh = r / HD;
    int h = (int)(bh % NH), b = (int)(bh / NH);
    h16 val = __float2half(0.f);
    if (s < S) val = v[((long long)(b * S + s)) * stride + colOff + h * HD + d];
    vT[idx] = val;
}

// ---------------- common asm helpers ----------------
__device__ __forceinline__ void mma16816(float c[4], const uint32_t a[4], const uint32_t b[2]) {
    asm volatile(
        "mma.sync.aligned.m16n8k16.row.col.f32.f16.f16.f32 "
        "{%0,%1,%2,%3}, {%4,%5,%6,%7}, {%8,%9}, {%0,%1,%2,%3};\n"
        : "+f"(c[0]), "+f"(c[1]), "+f"(c[2]), "+f"(c[3])
        : "r"(a[0]), "r"(a[1]), "r"(a[2]), "r"(a[3]), "r"(b[0]), "r"(b[1]));
}
__device__ __forceinline__ void cpasync16(uint32_t dst, const void* src, bool pred) {
    int sz = pred ? 16 : 0;
    asm volatile("cp.async.cg.shared.global [%0], [%1], 16, %2;\n"
                 :: "r"(dst), "l"(src), "r"(sz));
}
__device__ __forceinline__ void cp_commit() {
    asm volatile("cp.async.commit_group;\n" ::: "memory");
}
__device__ __forceinline__ void cp_wait0() { asm volatile("cp.async.wait_group 0;\n" ::: "memory"); }
__device__ __forceinline__ void cp_wait1() { asm volatile("cp.async.wait_group 1;\n" ::: "memory"); }
__device__ __forceinline__ void cp_wait2() { asm volatile("cp.async.wait_group 2;\n" ::: "memory"); }
__device__ __forceinline__ uint32_t pack_h2(float a, float b) {
    __half2 v = __floats2half2_rn(a, b);
    return *reinterpret_cast<uint32_t*>(&v);
}

// ---------------- cp.async pipelined batched fp16 GEMM ----------------
// gmode 0: C = scale*(A@W^T)+bias+residual -> Cf/Ch at [row*ldc+col]
// gmode 1: columns interleave (x1,x2); out = x1*gelu(x2) fp16 at [row*ldc+col/2]
#define KTILE    64
#define LDS_S    88
#define STG_ELE  (128 * LDS_S)
#define STAGES   4
#define SMEM_BYTES (2 * STAGES * STG_ELE * 2)

__global__ __launch_bounds__(512, 1) void gemm_kernel(
    const h16* __restrict__ A, const h16* __restrict__ W,
    const float* __restrict__ bias, const float* __restrict__ residual,
    float* __restrict__ Cf, h16* __restrict__ Ch,
    int M, int N, int K,
    long long aStride, long long wStride,
    long long cHi, long long cLo, int cDiv, int ldc, float scale, int gmode)
{
    extern __shared__ __align__(16) h16 sm[];
    h16* sA = sm;
    h16* sB = sm + STAGES * STG_ELE;

    int z = blockIdx.z;
    A += (long long)z * aStride;
    W += (long long)z * wStride;
    long long cOff = (long long)(z / cDiv) * cHi + (long long)(z % cDiv) * cLo;

    int tid = threadIdx.x;
    int lane = tid & 31, warp = tid >> 5;
    int wm = warp >> 2, wn = warp & 3;
    int rowBase = blockIdx.y * 128;
    int colBase = blockIdx.x * 128;
    bool wactive = (colBase + wn * 32) < N;

    uint32_t sA_u = (uint32_t)__cvta_generic_to_shared(sA);
    uint32_t sB_u = (uint32_t)__cvta_generic_to_shared(sB);

    int cr[2], cc[2];
#pragma unroll
    for (int jt = 0; jt < 2; ++jt) {
        int j = tid + jt * 512;
        cr[jt] = j >> 3;
        cc[jt] = (j & 7) << 3;
    }

    float acc[2][4][4];
#pragma unroll
    for (int i = 0; i < 2; i++)
#pragma unroll
        for (int j = 0; j < 4; j++)
#pragma unroll
            for (int l = 0; l < 4; l++) acc[i][j][l] = 0.f;

    int kTiles = K >> 6;

    auto issue = [&](int st, int k0) {
        uint32_t aBase = sA_u + st * (STG_ELE * 2);
        uint32_t bBase = sB_u + st * (STG_ELE * 2);
#pragma unroll
        for (int jt = 0; jt < 2; ++jt) {
            int r = cr[jt], c = cc[jt];
            uint32_t soff = (uint32_t)(r * LDS_S + c) * 2;
            int gr = rowBase + r;
            int grc = gr < M ? gr : (M - 1);
            cpasync16(aBase + soff, A + (long long)grc * K + k0 + c, gr < M);
            int gn = colBase + r;
            int gnc = gn < N ? gn : (N - 1);
            cpasync16(bBase + soff, W + (long long)gnc * K + k0 + c, gn < N);
        }
    };

#pragma unroll
    for (int f = 0; f < STAGES - 1; ++f) {
        if (f < kTiles) issue(f, f << 6);
        cp_commit();
    }

    for (int kt = 0; kt < kTiles; ++kt) {
        cp_wait2();
        __syncthreads();
        int nf = kt + STAGES - 1;
        if (nf < kTiles) issue(nf & (STAGES - 1), nf << 6);
        cp_commit();

        if (wactive) {
            const h16* Ah = sA + (kt & (STAGES - 1)) * STG_ELE;
            const h16* Bh = sB + (kt & (STAGES - 1)) * STG_ELE;
#pragma unroll
            for (int kk = 0; kk < KTILE; kk += 16) {
                uint32_t a[2][4];
#pragma unroll
                for (int mt = 0; mt < 2; ++mt) {
                    int r = wm * 32 + mt * 16 + (lane >> 2);
                    int c = kk + (lane & 3) * 2;
                    a[mt][0] = *(const uint32_t*)(Ah + r * LDS_S + c);
                    a[mt][1] = *(const uint32_t*)(Ah + (r + 8) * LDS_S + c);
                    a[mt][2] = *(const uint32_t*)(Ah + r * LDS_S + c + 8);
                    a[mt][3] = *(const uint32_t*)(Ah + (r + 8) * LDS_S + c + 8);
                }
#pragma unroll
                for (int nt = 0; nt < 4; ++nt) {
                    int n = wn * 32 + nt * 8 + (lane >> 2);
                    int c = kk + (lane & 3) * 2;
                    uint32_t b[2];
                    b[0] = *(const uint32_t*)(Bh + n * LDS_S + c);
                    b[1] = *(const uint32_t*)(Bh + n * LDS_S + c + 8);
#pragma unroll
                    for (int mt = 0; mt < 2; ++mt)
                        mma16816(acc[mt][nt], a[mt], b);
                }
            }
        }
    }

    if (wactive) {
#pragma unroll
        for (int mt = 0; mt < 2; ++mt)
#pragma unroll
            for (int nt = 0; nt < 4; ++nt) {
                int col = colBase + wn * 32 + nt * 8 + (lane & 3) * 2;
                if (col >= N) continue;
#pragma unroll
                for (int i = 0; i < 2; ++i) {
                    int row = rowBase + wm * 32 + mt * 16 + (lane >> 2) + i * 8;
                    if (row >= M) continue;
                    float v0 = acc[mt][nt][i * 2 + 0] * scale;
                    float v1 = acc[mt][nt][i * 2 + 1] * scale;
                    if (bias) { v0 += bias[col]; v1 += bias[col + 1]; }
                    if (gmode) {
                        // v0 = x1, v1 = x2 (interleaved weight layout); exact gelu
                        float gel = 0.5f * v1 * (1.0f + erff(v1 * 0.7071067811865476f));
                        Ch[cOff + (long long)row * ldc + (col >> 1)] = __float2half(v0 * gel);
                    } else {
                        long long o = cOff + (long long)row * ldc + col;
                        if (residual) { v0 += residual[o]; v1 += residual[o + 1]; }
                        if (Cf) { Cf[o] = v0; Cf[o + 1] = v1; }
                        if (Ch) { Ch[o] = __float2half(v0); Ch[o + 1] = __float2half(v1); }
                    }
                }
            }
    }
}

// ---------------- fused flash attention (unchanged from R13) ----------------
#define FKSTR 72
#define FVSTR 136
#define FQ_ELE (128 * FKSTR)
#define FK_ELE (128 * FKSTR)
#define FV_ELE (64 * FVSTR)
#define FSMEM_BYTES ((FQ_ELE + 2 * FK_ELE + 2 * FV_ELE) * 2)

__global__ __launch_bounds__(256, 1) void flash_kernel(
    const h16* __restrict__ qh, const h16* __restrict__ kh, const h16* __restrict__ vT,
    h16* __restrict__ att, int Stot, int Sval)
{
    extern __shared__ __align__(16) h16 fsm[];
    h16* sQ = fsm;
    h16* sK = fsm + FQ_ELE;
    h16* sV = fsm + FQ_ELE + 2 * FK_ELE;

    int tid = threadIdx.x;
    int lane = tid & 31, warp = tid >> 5;
    int l4 = lane & 3, ln4 = lane >> 2;
    int bh = blockIdx.y;
    int b = bh / NH, h = bh % NH;
    int qrow0 = blockIdx.x * 128;

    const h16* Qb = qh + (long long)bh * TQ * HD + (long long)qrow0 * HD;
    const h16* Kb = kh + (long long)bh * Stot * HD;
    const h16* Vb = vT + (long long)bh * HD * Stot;

    uint32_t sQ_u = (uint32_t)__cvta_generic_to_shared(sQ);
    uint32_t sK_u = (uint32_t)__cvta_generic_to_shared(sK);
    uint32_t sV_u = (uint32_t)__cvta_generic_to_shared(sV);

    int nk = Stot >> 7;

#pragma unroll
    for (int t = 0; t < 4; ++t) {
        int i = tid + t * 256;
        int r = i >> 3, c = (i & 7) << 3;
        cpasync16(sQ_u + (uint32_t)(r * FKSTR + c) * 2, Qb + r * HD + c, true);
    }
    cp_commit();

    auto issueKV = [&](int st, int kt) {
        uint32_t kb = sK_u + st * (FK_ELE * 2);
        uint32_t vb = sV_u + st * (FV_ELE * 2);
#pragma unroll
        for (int t = 0; t < 4; ++t) {
            int i = tid + t * 256;
            int r = i >> 3, c = (i & 7) << 3;
            cpasync16(kb + (uint32_t)(r * FKSTR + c) * 2, Kb + (long long)(kt * 128 + r) * HD + c, true);
            int vr = i >> 4, vc = (i & 15) << 3;
            cpasync16(vb + (uint32_t)(vr * FVSTR + vc) * 2, Vb + (long long)vr * Stot + kt * 128 + vc, true);
        }
    };
    issueKV(0, 0);
    cp_commit();

    cp_wait1();
    __syncthreads();

    uint32_t qa[4][4];
    {
        const h16* Qw = sQ + (warp * 16) * FKSTR;
#pragma unroll
        for (int kk = 0; kk < 4; ++kk) {
            int c = kk * 16 + l4 * 2;
            qa[kk][0] = *(const uint32_t*)(Qw + ln4 * FKSTR + c);
            qa[kk][1] = *(const uint32_t*)(Qw + (ln4 + 8) * FKSTR + c);
            qa[kk][2] = *(const uint32_t*)(Qw + ln4 * FKSTR + c + 8);
            qa[kk][3] = *(const uint32_t*)(Qw + (ln4 + 8) * FKSTR + c + 8);
        }
    }

    float m0 = -1e30f, m1 = -1e30f, le0 = 0.f, le1 = 0.f;
    float oc[8][4];
#pragma unroll
    for (int n = 0; n < 8; ++n)
#pragma unroll
        for (int c = 0; c < 4; ++c) oc[n][c] = 0.f;

    bool doMask = (Sval < Stot);

    for (int kt = 0; kt < nk; ++kt) {
        if (kt + 1 < nk) { issueKV((kt + 1) & 1, kt + 1); cp_commit(); cp_wait1(); }
        else cp_wait0();
        __syncthreads();

        const h16* Kt = sK + (kt & 1) * FK_ELE;
        const h16* Vt = sV + (kt & 1) * FV_ELE;

        float sc[16][4];
#pragma unroll
        for (int j = 0; j < 16; ++j)
#pragma unroll
            for (int c = 0; c < 4; ++c) sc[j][c] = 0.f;
#pragma unroll
        for (int kk = 0; kk < 4; ++kk) {
#pragma unroll
            for (int j = 0; j < 16; ++j) {
                uint32_t kb2[2];
                const h16* kp = Kt + (j * 8 + ln4) * FKSTR + kk * 16 + l4 * 2;
                kb2[0] = *(const uint32_t*)(kp);
                kb2[1] = *(const uint32_t*)(kp + 8);
                mma16816(sc[j], qa[kk], kb2);
            }
        }

        if (doMask) {
            int base = kt * 128 + l4 * 2;
#pragma unroll
            for (int j = 0; j < 16; ++j) {
                int col = base + j * 8;
                if (col >= Sval)     { sc[j][0] = -1e30f; sc[j][2] = -1e30f; }
                if (col + 1 >= Sval) { sc[j][1] = -1e30f; sc[j][3] = -1e30f; }
            }
        }

        float mr0 = -1e30f, mr1 = -1e30f;
#pragma unroll
        for (int j = 0; j < 16; ++j) {
            mr0 = fmaxf(mr0, fmaxf(sc[j][0], sc[j][1]));
            mr1 = fmaxf(mr1, fmaxf(sc[j][2], sc[j][3]));
        }
        mr0 = fmaxf(mr0, __shfl_xor_sync(0xffffffffu, mr0, 1));
        mr0 = fmaxf(mr0, __shfl_xor_sync(0xffffffffu, mr0, 2));
        mr1 = fmaxf(mr1, __shfl_xor_sync(0xffffffffu, mr1, 1));
        mr1 = fmaxf(mr1, __shfl_xor_sync(0xffffffffu, mr1, 2));
        float mn0 = fmaxf(m0, mr0), mn1 = fmaxf(m1, mr1);
        float a0 = expf(m0 - mn0), a1 = expf(m1 - mn1);
        float s0 = 0.f, s1 = 0.f;
#pragma unroll
        for (int j = 0; j < 16; ++j) {
            sc[j][0] = expf(sc[j][0] - mn0);
            sc[j][1] = expf(sc[j][1] - mn0);
            sc[j][2] = expf(sc[j][2] - mn1);
            sc[j][3] = expf(sc[j][3] - mn1);
            s0 += sc[j][0] + sc[j][1];
            s1 += sc[j][2] + sc[j][3];
        }
        s0 += __shfl_xor_sync(0xffffffffu, s0, 1);
        s0 += __shfl_xor_sync(0xffffffffu, s0, 2);
        s1 += __shfl_xor_sync(0xffffffffu, s1, 1);
        s1 += __shfl_xor_sync(0xffffffffu, s1, 2);
        le0 = a0 * le0 + s0;
        le1 = a1 * le1 + s1;
        m0 = mn0; m1 = mn1;
#pragma unroll
        for (int n = 0; n < 8; ++n) {
            oc[n][0] *= a0; oc[n][1] *= a0;
            oc[n][2] *= a1; oc[n][3] *= a1;
        }

#pragma unroll
        for (int kk = 0; kk < 8; ++kk) {
            int j0 = kk * 2, j1 = kk * 2 + 1;
            uint32_t pa[4];
            pa[0] = pack_h2(sc[j0][0], sc[j0][1]);
            pa[1] = pack_h2(sc[j0][2], sc[j0][3]);
            pa[2] = pack_h2(sc[j1][0], sc[j1][1]);
            pa[3] = pack_h2(sc[j1][2], sc[j1][3]);
#pragma unroll
            for (int n = 0; n < 8; ++n) {
                uint32_t vb2[2];
                const h16* vp = Vt + (n * 8 + ln4) * FVSTR + kk * 16 + l4 * 2;
                vb2[0] = *(const uint32_t*)(vp);
                vb2[1] = *(const uint32_t*)(vp + 8);
                mma16816(oc[n], pa, vb2);
            }
        }
        __syncthreads();
    }

    float il0 = 1.f / le0, il1 = 1.f / le1;
    int r0 = qrow0 + warp * 16 + ln4;
    int r1 = r0 + 8;
    long long o0 = ((long long)(b * TQ) + r0) * HID + h * HD;
    long long o1 = ((long long)(b * TQ) + r1) * HID + h * HD;
#pragma unroll
    for (int n = 0; n < 8; ++n) {
        int d = n * 8 + l4 * 2;
        uint32_t v0 = pack_h2(oc[n][0] * il0, oc[n][1] * il0);
        uint32_t v1 = pack_h2(oc[n][2] * il1, oc[n][3] * il1);
        *(uint32_t*)(att + o0 + d) = v0;
        *(uint32_t*)(att + o1 + d) = v1;
    }
}

// ---------------- host glue ----------------
static void gemm(const h16* A, const h16* W, const float* bias, const float* res,
                 float* Cf, h16* Ch, int M, int N, int K, int Z,
                 long long aS, long long wS, long long cHi, long long cLo, int cDiv,
                 int ldc, float scale, int gmode = 0) {
    dim3 g((N + 127) / 128, (M + 127) / 128, Z);
    gemm_kernel<<<g, 512, SMEM_BYTES>>>(A, W, bias, res, Cf, Ch, M, N, K, aS, wS, cHi, cLo, cDiv, ldc, scale, gmode);
}

static void f2h(const float* in, h16* out, long long n) {
    f2h_kernel<<<(unsigned)((n + 255) / 256), 256>>>(in, out, n);
}

extern "C" void kernel_launch(void* const* d_in, const int* in_sizes, int n_in,
                              void* d_out, int out_size) {
    const float* x     = (const float*)d_in[0];
    const float* enc   = (const float*)d_in[1];
    const float* ln1g  = (const float*)d_in[2];
    const float* ln1b  = (const float*)d_in[3];
    const float* ln2g  = (const float*)d_in[4];
    const float* ln2b  = (const float*)d_in[5];
    const float* ln3g  = (const float*)d_in[6];
    const float* ln3b  = (const float*)d_in[7];
    const float* wq1   = (const float*)d_in[8];
    const float* wk1   = (const float*)d_in[9];
    const float* wv1   = (const float*)d_in[10];
    const float* wo1   = (const float*)d_in[11];
    const float* bo1   = (const float*)d_in[12];
    const float* wq2   = (const float*)d_in[13];
    const float* wk2   = (const float*)d_in[14];
    const float* wv2   = (const float*)d_in[15];
    const float* wo2   = (const float*)d_in[16];
    const float* bo2   = (const float*)d_in[17];
    const float* wgg   = (const float*)d_in[18];
    const float* bgg   = (const float*)d_in[19];
    const float* wff   = (const float*)d_in[20];
    const float* bff   = (const float*)d_in[21];
    float* out = (float*)d_out;

    static bool attr_done = false;
    if (!attr_done) {
        cudaFuncSetAttribute(gemm_kernel, cudaFuncAttributeMaxDynamicSharedMemorySize, SMEM_BYTES);
        cudaFuncSetAttribute(flash_kernel, cudaFuncAttributeMaxDynamicSharedMemorySize, FSMEM_BYTES);
        attr_done = true;
    }

    h16 *h, *pqkv, *pq, *pkv, *qh, *kh, *vT, *att, *ff, *encb;
    float *xcur, *bggp;
    cudaGetSymbolAddress((void**)&h,     g_h);
    cudaGetSymbolAddress((void**)&pqkv,  g_pqkv);
    cudaGetSymbolAddress((void**)&pq,    g_pq);
    cudaGetSymbolAddress((void**)&pkv,   g_pkv);
    cudaGetSymbolAddress((void**)&qh,    g_qh);
    cudaGetSymbolAddress((void**)&kh,    g_kh);
    cudaGetSymbolAddress((void**)&vT,    g_vT);
    cudaGetSymbolAddress((void**)&att,   g_att);
    cudaGetSymbolAddress((void**)&xcur,  g_x);
    cudaGetSymbolAddress((void**)&ff,    g_ff);
    cudaGetSymbolAddress((void**)&encb,  g_enc);
    cudaGetSymbolAddress((void**)&bggp,  g_bggp);

    h16 *Wqkv1, *Wo1, *Wq2, *Wkv2, *Wo2, *Wgg, *Wff;
    cudaGetSymbolAddress((void**)&Wqkv1, g_wqkv1h);
    cudaGetSymbolAddress((void**)&Wo1,   g_wo1h);
    cudaGetSymbolAddress((void**)&Wq2,   g_wq2h);
    cudaGetSymbolAddress((void**)&Wkv2,  g_wkv2h);
    cudaGetSymbolAddress((void**)&Wo2,   g_wo2h);
    cudaGetSymbolAddress((void**)&Wgg,   g_wggh);
    cudaGetSymbolAddress((void**)&Wff,   g_wffh);

    // weight + encoder conversion (QKV packed, K/V cross packed, geglu permuted)
    f2h(wq1, Wqkv1,                 (long long)HID * HID);
    f2h(wk1, Wqkv1 + HID * HID,     (long long)HID * HID);
    f2h(wv1, Wqkv1 + 2 * HID * HID, (long long)HID * HID);
    f2h(wo1, Wo1, (long long)HID * HID);
    f2h(wq2, Wq2, (long long)HID * HID);
    f2h(wk2, Wkv2,                (long long)HID * CROSSD);
    f2h(wv2, Wkv2 + HID * CROSSD, (long long)HID * CROSSD);
    f2h(wo2, Wo2, (long long)HID * HID);
    {
        long long n = (long long)2 * FFD * HID;
        permute_wgg_kernel<<<(unsigned)((n + 255) / 256), 256>>>(wgg, Wgg);
        permute_bgg_kernel<<<(2 * FFD + 255) / 256, 256>>>(bgg, bggp);
    }
    f2h(wff, Wff, (long long)HID * FFD);
    f2h(enc, encb, (long long)MENC * CROSSD);

    // ---- self attention ----
    ln_kernel<<<M1, 256>>>(x, ln1g, ln1b, h);
    gemm(h, Wqkv1, nullptr, nullptr, nullptr, pqkv, M1, 3 * HID, HID, 1, 0, 0, 0, 0, 1, 3 * HID, 1.f);
    {
        long long nq = (long long)NBH * TQ * HD;
        reshape_q_kernel<<<(unsigned)((nq + 255) / 256), 256>>>(pqkv, qh, 3 * HID, 0);
        reshape_k_kernel<<<(unsigned)((nq + 255) / 256), 256>>>(pqkv, kh, TQ, TQ, 3 * HID, HID);
        reshape_vT_kernel<<<(unsigned)((nq + 255) / 256), 256>>>(pqkv, vT, TQ, TQ, 3 * HID, 2 * HID);
    }
    flash_kernel<<<dim3(TQ / 128, NBH), 256, FSMEM_BYTES>>>(qh, kh, vT, att, TQ, TQ);
    gemm(att, Wo1, bo1, x, xcur, nullptr, M1, HID, HID, 1, 0, 0, 0, 0, 1, HID, 1.f);

    // ---- cross attention ----
    ln_kernel<<<M1, 256>>>(xcur, ln2g, ln2b, h);
    gemm(h, Wq2, nullptr, nullptr, nullptr, pq, M1, HID, HID, 1, 0, 0, 0, 0, 1, HID, 1.f);
    gemm(encb, Wkv2, nullptr, nullptr, nullptr, pkv, MENC, 2 * HID, CROSSD, 1, 0, 0, 0, 0, 1, 2 * HID, 1.f);
    {
        long long nq = (long long)NBH * TQ * HD;
        long long nk = (long long)NBH * SPAD * HD;
        reshape_q_kernel<<<(unsigned)((nq + 255) / 256), 256>>>(pq, qh, HID, 0);
        reshape_k_kernel<<<(unsigned)((nk + 255) / 256), 256>>>(pkv, kh, SENC, SPAD, 2 * HID, 0);
        reshape_vT_kernel<<<(unsigned)((nk + 255) / 256), 256>>>(pkv, vT, SENC, SPAD, 2 * HID, HID);
    }
    flash_kernel<<<dim3(TQ / 128, NBH), 256, FSMEM_BYTES>>>(qh, kh, vT, att, SPAD, SENC);
    gemm(att, Wo2, bo2, xcur, xcur, nullptr, M1, HID, HID, 1, 0, 0, 0, 0, 1, HID, 1.f);

    // ---- GEGLU FF (activation fused into GEMM epilogue) ----
    ln_kernel<<<M1, 256>>>(xcur, ln3g, ln3b, h);
    gemm(h, Wgg, bggp, nullptr, nullptr, ff, M1, 2 * FFD, HID, 1, 0, 0, 0, 0, 1, FFD, 1.f, 1);
    gemm(ff, Wff, bff, xcur, out, nullptr, M1, HID, FFD, 1, 0, 0, 0, 0, 1, HID, 1.f);

    (void)in_sizes; (void)n_in; (void)out_size;
}